// round 13
// baseline (speedup 1.0000x reference)
#include <cuda_runtime.h>
#include <cuda_fp16.h>
#include <math.h>
#include <stdint.h>

// ---------------- problem constants ----------------
#define S_LEN 4096
#define HID   2048
#define NH    8
#define NVH   16
#define DK    128
#define DV    128
#define KEY_DIM  (NH*DK)    // 1024
#define VAL_DIM  (NVH*DV)   // 2048
#define CONV  4
#define EPS_  1e-6f
#define SCALE_ 0.08838834764831845f   // 128^-0.5

// ---------------- workspace -------------------------------------------------
static constexpr size_t SZ_QPRE = (size_t)S_LEN * KEY_DIM;
static constexpr size_t SZ_VPRE = (size_t)S_LEN * VAL_DIM;
static constexpr size_t SZ_AB   = (size_t)S_LEN * NVH;
static constexpr size_t SZ_C    = (size_t)S_LEN * NH;
static constexpr size_t SZ_X    = (size_t)S_LEN * HID;
static constexpr size_t SZ_WQK  = (size_t)KEY_DIM * HID;
static constexpr size_t SZ_WV   = (size_t)VAL_DIM * HID;

static constexpr size_t OF_QPRE = 0;
static constexpr size_t OF_KPRE = OF_QPRE + SZ_QPRE;
static constexpr size_t OF_VPRE = OF_KPRE + SZ_QPRE;
static constexpr size_t OF_GATE = OF_VPRE + SZ_VPRE;
static constexpr size_t OF_QN   = OF_GATE + SZ_VPRE;
static constexpr size_t OF_KN   = OF_QN + SZ_QPRE;
static constexpr size_t OF_VN   = OF_KN + SZ_QPRE;
static constexpr size_t OF_DB   = OF_VN + SZ_VPRE;   // float2 per (t,h)
static constexpr size_t OF_CQ   = OF_DB + 2*SZ_AB;   // float2 (C1,C2) per (t,hk)
static constexpr size_t OF_O    = OF_CQ + 2*SZ_C;
// fp16 buffers (element counts halved into float units)
static constexpr size_t OF_XH   = OF_O + SZ_VPRE;
static constexpr size_t OF_WQH  = OF_XH + SZ_X/2;
static constexpr size_t OF_WKH  = OF_WQH + SZ_WQK/2;
static constexpr size_t OF_WVH  = OF_WKH + SZ_WQK/2;
static constexpr size_t OF_WGH  = OF_WVH + SZ_WV/2;
static constexpr size_t OF_WOH  = OF_WGH + SZ_WV/2;
static constexpr size_t OF_OGH  = OF_WOH + SZ_WV/2;
static constexpr size_t WS_TOTAL = OF_OGH + SZ_VPRE/2;

__device__ float g_ws_gdn[WS_TOTAL];

// ---------------- cp.async helpers -----------------------------------------
__device__ __forceinline__ void cp16(void* s, const void* g) {
    asm volatile("cp.async.ca.shared.global [%0], [%1], 16;"
                 :: "r"((uint32_t)__cvta_generic_to_shared(s)), "l"(g));
}
__device__ __forceinline__ void cp8(void* s, const void* g) {
    asm volatile("cp.async.ca.shared.global [%0], [%1], 8;"
                 :: "r"((uint32_t)__cvta_generic_to_shared(s)), "l"(g));
}
__device__ __forceinline__ void cp_commit() {
    asm volatile("cp.async.commit_group;");
}

// ---------------- fp32 -> fp16 conversion ----------------------------------
__global__ __launch_bounds__(256) void cvt_h_kernel(
    const float* __restrict__ in, __half* __restrict__ out, int n)
{
    int i = (blockIdx.x * 256 + threadIdx.x) * 8;
    if (i >= n) return;
    float4 v0 = *(const float4*)(in + i);
    float4 v1 = *(const float4*)(in + i + 4);
    __half2 h[4];
    h[0] = __floats2half2_rn(v0.x, v0.y);
    h[1] = __floats2half2_rn(v0.z, v0.w);
    h[2] = __floats2half2_rn(v1.x, v1.y);
    h[3] = __floats2half2_rn(v1.z, v1.w);
    *(uint4*)(out + i) = *(uint4*)h;
}

// ================= fp16 tensor-core GEMM (k32 stages, 4-deep ring) =========
#define GBM 128
#define GBN 128
#define KC  32
#define PADH 40
#define STAGE_H (2 * GBM * PADH)
#define GDYN_SMEM (4 * STAGE_H * 2)    // 81920 bytes

__device__ __forceinline__ void mma_f16(float* c, const uint32_t* a, const uint32_t* b) {
    asm volatile(
        "mma.sync.aligned.m16n8k16.row.col.f32.f16.f16.f32 "
        "{%0,%1,%2,%3}, {%4,%5,%6,%7}, {%8,%9}, {%0,%1,%2,%3};"
        : "+f"(c[0]), "+f"(c[1]), "+f"(c[2]), "+f"(c[3])
        : "r"(a[0]), "r"(a[1]), "r"(a[2]), "r"(a[3]), "r"(b[0]), "r"(b[1]));
}

__device__ __forceinline__ void ldsm4(uint32_t* r, uint32_t addr) {
    asm volatile("ldmatrix.sync.aligned.m8n8.x4.shared.b16 {%0,%1,%2,%3}, [%4];"
                 : "=r"(r[0]), "=r"(r[1]), "=r"(r[2]), "=r"(r[3]) : "r"(addr));
}

__device__ __forceinline__ void gemm_core(
    const __half* __restrict__ A, const __half* __restrict__ B,
    float* __restrict__ C, int n0, int ldc, int K)
{
    extern __shared__ __half smh[];
    uint32_t sbase = (uint32_t)__cvta_generic_to_shared(smh);

    int tid = threadIdx.x;
    int warp = tid >> 5;
    int lane = tid & 31;
    int gid = lane >> 2;
    int tig = lane & 3;

    int m0 = blockIdx.y * GBM;
    int wm = (warp >> 2) * 64;
    int wn = (warp & 3) * 32;

    int lrow = tid >> 1;
    int lk   = (tid & 1) * 16;
    const __half* Ag = A + (size_t)(m0 + lrow) * K + lk;
    const __half* Bg = B + (size_t)(n0 + lrow) * K + lk;
    int sA = lrow * PADH + lk;
    int sB = GBM * PADH + lrow * PADH + lk;

    int arow = wm + (lane & 15);
    int akh  = (lane >> 4) * 8;
    int brow = wn + (lane & 7) + ((lane >> 4) << 3);
    int bkh  = ((lane >> 3) & 1) * 8;

    float acc[4][4][4];
#pragma unroll
    for (int i = 0; i < 4; i++)
#pragma unroll
        for (int j = 0; j < 4; j++)
#pragma unroll
            for (int r = 0; r < 4; r++) acc[i][j][r] = 0.f;

    int kIters = K / KC;

#pragma unroll
    for (int s = 0; s < 3; s++) {
        __half* stg = smh + s * STAGE_H;
        cp16(stg + sA,     Ag + (size_t)s * KC);
        cp16(stg + sA + 8, Ag + (size_t)s * KC + 8);
        cp16(stg + sB,     Bg + (size_t)s * KC);
        cp16(stg + sB + 8, Bg + (size_t)s * KC + 8);
        cp_commit();
    }

    for (int it = 0; it < kIters; it++) {
        asm volatile("cp.async.wait_group 2;");
        __syncthreads();

        if (it + 3 < kIters) {
            __half* stg = smh + ((it + 3) & 3) * STAGE_H;
            cp16(stg + sA,     Ag + (size_t)(it + 3) * KC);
            cp16(stg + sA + 8, Ag + (size_t)(it + 3) * KC + 8);
            cp16(stg + sB,     Bg + (size_t)(it + 3) * KC);
            cp16(stg + sB + 8, Bg + (size_t)(it + 3) * KC + 8);
        }
        cp_commit();

        uint32_t stg = sbase + ((it & 3) * STAGE_H) * 2;

#pragma unroll
        for (int sub = 0; sub < 2; sub++) {
            int cb = sub * 16;
            uint32_t aaddr = stg + (uint32_t)(arow * PADH + cb + akh) * 2;
            uint32_t baddr = stg + (uint32_t)(GBM * PADH + brow * PADH + cb + bkh) * 2;

            uint32_t af[4][4], bfr[2][4];
#pragma unroll
            for (int mt = 0; mt < 4; mt++) ldsm4(af[mt], aaddr + mt * 16 * PADH * 2);
#pragma unroll
            for (int pt = 0; pt < 2; pt++) ldsm4(bfr[pt], baddr + pt * 16 * PADH * 2);

#pragma unroll
            for (int mt = 0; mt < 4; mt++)
#pragma unroll
                for (int nt = 0; nt < 4; nt++)
                    mma_f16(acc[mt][nt], af[mt], &bfr[nt >> 1][(nt & 1) * 2]);
        }
    }

#pragma unroll
    for (int mt = 0; mt < 4; mt++) {
#pragma unroll
        for (int nt = 0; nt < 4; nt++) {
            int m = m0 + wm + mt * 16 + gid;
            int n = n0 + wn + nt * 8 + tig * 2;
            *(float2*)&C[(size_t)m * ldc + n] = make_float2(acc[mt][nt][0], acc[mt][nt][1]);
            *(float2*)&C[(size_t)(m + 8) * ldc + n] = make_float2(acc[mt][nt][2], acc[mt][nt][3]);
        }
    }
}

// merged x-projection: blockIdx.x 0..7 Wq, 8..15 Wk, 16..31 Wv, 32..47 Wg
__global__ __launch_bounds__(256, 2) void gemm_x4(
    const __half* __restrict__ x,
    const __half* __restrict__ Wq, const __half* __restrict__ Wk,
    const __half* __restrict__ Wv, const __half* __restrict__ Wg,
    float* __restrict__ qpre, float* __restrict__ kpre,
    float* __restrict__ vpre, float* __restrict__ gate)
{
    int bx = blockIdx.x;
    const __half* B; float* C; int n0; int ldc;
    if (bx < 8)       { B = Wq; C = qpre; n0 = bx * 128;        ldc = KEY_DIM; }
    else if (bx < 16) { B = Wk; C = kpre; n0 = (bx - 8) * 128;  ldc = KEY_DIM; }
    else if (bx < 32) { B = Wv; C = vpre; n0 = (bx - 16) * 128; ldc = VAL_DIM; }
    else              { B = Wg; C = gate; n0 = (bx - 32) * 128; ldc = VAL_DIM; }
    gemm_core(x, B, C, n0, ldc, HID);
}

__global__ __launch_bounds__(256, 2) void gemm_h(
    const __half* __restrict__ A, const __half* __restrict__ B,
    float* __restrict__ C, int N, int K)
{
    gemm_core(A, B, C, blockIdx.x * GBN, N, K);
}

// ---------------- fused a/b projection + decay/beta -----------------------
__global__ __launch_bounds__(128) void gemv_ab(
    const float* __restrict__ x, const float* __restrict__ Wa,
    const float* __restrict__ Wb, const float* __restrict__ A_log,
    const float* __restrict__ dt_bias, float2* __restrict__ db)
{
    __shared__ float xs[8][260];
    __shared__ float was[16][260];
    __shared__ float wbs[16][260];

    int tid = threadIdx.x;
    int row = tid >> 4, n = tid & 15;
    int r0 = blockIdx.x * 8;

    float acc_a = 0.f, acc_b = 0.f;
    for (int kc = 0; kc < HID; kc += 256) {
        __syncthreads();
        int lr = tid >> 4, lo = (tid & 15) * 16;
#pragma unroll
        for (int j = 0; j < 16; j += 4)
            *(float4*)&xs[lr][lo + j] = *(const float4*)&x[(size_t)(r0 + lr) * HID + kc + lo + j];
        int wr = tid >> 3, wo = (tid & 7) * 32;
#pragma unroll
        for (int j = 0; j < 32; j += 4) {
            *(float4*)&was[wr][wo + j] = *(const float4*)&Wa[(size_t)wr * HID + kc + wo + j];
            *(float4*)&wbs[wr][wo + j] = *(const float4*)&Wb[(size_t)wr * HID + kc + wo + j];
        }
        __syncthreads();
#pragma unroll 8
        for (int j = 0; j < 256; j += 4) {
            float4 xv = *(float4*)&xs[row][j];
            float4 wa = *(float4*)&was[n][j];
            float4 wb = *(float4*)&wbs[n][j];
            acc_a += xv.x*wa.x + xv.y*wa.y + xv.z*wa.z + xv.w*wa.w;
            acc_b += xv.x*wb.x + xv.y*wb.y + xv.z*wb.z + xv.w*wb.w;
        }
    }
    float a = acc_a + dt_bias[n];
    float sp = (a > 20.f) ? a : log1pf(expf(a));
    float decay = expf(-expf(A_log[n]) * sp);
    float beta = 1.f / (1.f + expf(-acc_b));
    db[(size_t)(r0 + row) * NVH + n] = make_float2(decay, beta);
}

// ---------------- conv + silu + l2norm for q/k ----------------------------
__global__ __launch_bounds__(128) void convqk_kernel(
    const float* __restrict__ pre, const float* __restrict__ cw,
    float* __restrict__ out, float scale)
{
    int t = blockIdx.x >> 3;
    int h = blockIdx.x & 7;
    int c = threadIdx.x;
    int ch = h * DK + c;
    float y = 0.f;
#pragma unroll
    for (int j = 0; j < CONV; j++) {
        int tt = t - (CONV-1) + j;
        float xv = (tt >= 0) ? pre[(size_t)tt * KEY_DIM + ch] : 0.f;
        y = fmaf(xv, cw[ch*CONV + j], y);
    }
    y = y / (1.f + expf(-y));
    float ss = y * y;
#pragma unroll
    for (int off = 16; off; off >>= 1) ss += __shfl_xor_sync(0xffffffffu, ss, off);
    __shared__ float wss[4];
    if ((threadIdx.x & 31) == 0) wss[threadIdx.x >> 5] = ss;
    __syncthreads();
    float tot = wss[0] + wss[1] + wss[2] + wss[3];
    out[(size_t)t * KEY_DIM + ch] = y * rsqrtf(tot + EPS_) * scale;
}

// ---------------- conv + silu for v ---------------------------------------
__global__ __launch_bounds__(256) void convv_kernel(
    const float* __restrict__ pre, const float* __restrict__ cw,
    float* __restrict__ out)
{
    int idx = blockIdx.x * blockDim.x + threadIdx.x;
    int t = idx >> 11;
    int ch = idx & 2047;
    float y = 0.f;
#pragma unroll
    for (int j = 0; j < CONV; j++) {
        int tt = t - (CONV-1) + j;
        float xv = (tt >= 0) ? pre[(size_t)tt * VAL_DIM + ch] : 0.f;
        y = fmaf(xv, cw[ch*CONV + j], y);
    }
    out[idx] = y / (1.f + expf(-y));
}

// ---------------- (C1,C2)[t][hk] = (k_{t+1}.k_t, k_{t+2}.k_t) --------------
__global__ __launch_bounds__(256) void dotck_kernel(
    const float* __restrict__ k, float2* __restrict__ Cq)
{
    int warp = threadIdx.x >> 5;
    int lane = threadIdx.x & 31;
    int idx = blockIdx.x * 8 + warp;       // t*NH + hk
    int t = idx >> 3, hk = idx & 7;
    const float* k0 = k + (size_t)t * KEY_DIM + hk * DK + lane * 4;
    float4 a = *(const float4*)k0;
    float c1 = 0.f, c2 = 0.f;
    if (t + 1 < S_LEN) {
        float4 b = *(const float4*)(k0 + KEY_DIM);
        c1 = a.x*b.x + a.y*b.y + a.z*b.z + a.w*b.w;
    }
    if (t + 2 < S_LEN) {
        float4 b = *(const float4*)(k0 + 2 * KEY_DIM);
        c2 = a.x*b.x + a.y*b.y + a.z*b.z + a.w*b.w;
    }
#pragma unroll
    for (int off = 16; off; off >>= 1) {
        c1 += __shfl_xor_sync(0xffffffffu, c1, off);
        c2 += __shfl_xor_sync(0xffffffffu, c2, off);
    }
    if (lane == 0) Cq[(size_t)t * NH + hk] = make_float2(c1, c2);
}

// ---------------- delta-rule scan v6: two-step lookahead -------------------
// W_t = k_{t+2}.S_{t-1} (tree has ~1.5 steps of slack).
// Q_t = d_{t-1}*W_{t-1} + C2[t-1]*delta_{t-1}   (scalar)
// P1_{t+1} = d_t*Q_t + C1[t]*delta_t            (scalar)
// delta_t = (v_t - d_t*P1_t)*beta_t — serial chain is 3 scalar FMAs.
#define CH 16
#define KSTR 292   // 18 rows * 16 + 4 ; 292 % 8 == 4 (conflict-free)
#define QSTR 260   // 16 rows * 16 + 4

__global__ __launch_bounds__(128) void scan_kernel(
    const float* __restrict__ k, const float* __restrict__ q,
    const float* __restrict__ v, const float2* __restrict__ db,
    const float2* __restrict__ Cq, float* __restrict__ o)
{
    __shared__ float ksw[2][8 * KSTR];
    __shared__ float qsw[2][8 * QSTR];
    __shared__ float vs[2][CH][16];
    __shared__ float2 dbs[2][CH];
    __shared__ float2 cs[2][CH];

    int h = blockIdx.x >> 3;
    int hk = h >> 1;
    int colbase = (blockIdx.x & 7) * 16;
    int tid = threadIdx.x;
    int w = tid >> 5, lane = tid & 31;
    int g = lane >> 3, s = lane & 7;
    int col = colbase + w * 4 + g;

    int plr = tid >> 3;     // 0..15
    int pgp = tid & 7;
    int vr = tid >> 2;

    const float* kbase = k + hk * DK;
    const float* qbase = q + hk * DK;
    const float* vbase = v + h * DV + colbase + (tid & 3) * 4;
    const float2* dbase = db + h;
    const float2* cbase = Cq + hk;
    float* obase = o + h * DV + col;

    // ---- issue chunk 0 (rows 0..CH+1: two overlap rows) ----
    {
        const float* krow = kbase + (size_t)plr * KEY_DIM + pgp * 16;
        const float* qrow = qbase + (size_t)plr * KEY_DIM + pgp * 16;
#pragma unroll
        for (int j = 0; j < 4; j++) {
            cp16(&ksw[0][pgp * KSTR + plr * 16 + j * 4], krow + j * 4);
            cp16(&qsw[0][pgp * QSTR + plr * 16 + j * 4], qrow + j * 4);
        }
        if (tid < 16) {
            int ro = tid >> 3;                 // 0 or 1
            int gg = tid & 7;
            const float* kov = kbase + (size_t)(CH + ro) * KEY_DIM + gg * 16;
#pragma unroll
            for (int j = 0; j < 4; j++)
                cp16(&ksw[0][gg * KSTR + (CH + ro) * 16 + j * 4], kov + j * 4);
        }
        if (tid < 64) cp16(&vs[0][vr][(tid & 3) * 4], vbase + (size_t)vr * VAL_DIM);
        if (tid < CH) cp8(&dbs[0][tid], dbase + (size_t)tid * NVH);
        if (tid < CH) cp8(&cs[0][tid], cbase + (size_t)tid * NH);
        cp_commit();
    }

    float S[16];
#pragma unroll
    for (int i = 0; i < 16; i++) S[i] = 0.f;
    float P1 = 0.f;
    float Wprev = 0.f, dprev = 0.f, dlprev = 0.f, c2prev = 0.f;
    float kc[16], kn[16];
    bool kinit = false;

    int buf = 0;
    const int NCH = S_LEN / CH;
    for (int c = 0; c < NCH; c++) {
        if (c + 1 < NCH) {
            int t0 = (c + 1) * CH;
            int p = buf ^ 1;
            const float* krow = kbase + (size_t)(t0 + plr) * KEY_DIM + pgp * 16;
            const float* qrow = qbase + (size_t)(t0 + plr) * KEY_DIM + pgp * 16;
#pragma unroll
            for (int j = 0; j < 4; j++) {
                cp16(&ksw[p][pgp * KSTR + plr * 16 + j * 4], krow + j * 4);
                cp16(&qsw[p][pgp * QSTR + plr * 16 + j * 4], qrow + j * 4);
            }
            if (tid < 16) {
                int ro = tid >> 3;
                int gg = tid & 7;
                int ovr = t0 + CH + ro; if (ovr > S_LEN - 1) ovr = S_LEN - 1;
                const float* kov = kbase + (size_t)ovr * KEY_DIM + gg * 16;
#pragma unroll
                for (int j = 0; j < 4; j++)
                    cp16(&ksw[p][gg * KSTR + (CH + ro) * 16 + j * 4], kov + j * 4);
            }
            if (tid < 64) cp16(&vs[p][vr][(tid & 3) * 4], vbase + (size_t)(t0 + vr) * VAL_DIM);
            if (tid < CH) cp8(&dbs[p][tid], dbase + (size_t)(t0 + tid) * NVH);
            if (tid < CH) cp8(&cs[p][tid], cbase + (size_t)(t0 + tid) * NH);
            cp_commit();
            asm volatile("cp.async.wait_group 1;");
        } else {
            asm volatile("cp.async.wait_group 0;");
        }
        __syncthreads();

        if (!kinit) {   // first chunk: kc = k_0, kn = k_1
#pragma unroll
            for (int i = 0; i < 16; i += 4) {
                *(float4*)&kc[i] = *(const float4*)&ksw[0][s * KSTR + i];
                *(float4*)&kn[i] = *(const float4*)&ksw[0][s * KSTR + 16 + i];
            }
            kinit = true;
        }

        int t0 = c * CH;
        float* ob = obase + (size_t)t0 * VAL_DIM;
#pragma unroll
        for (int tt = 0; tt < CH; tt++) {
            // load k_{t+2}, q_t
            float kn2[16], qc[16];
#pragma unroll
            for (int i = 0; i < 16; i += 4) {
                *(float4*)&kn2[i] = *(const float4*)&ksw[buf][s * KSTR + (tt + 2) * 16 + i];
                *(float4*)&qc[i]  = *(const float4*)&qsw[buf][s * QSTR + tt * 16 + i];
            }
            float vc = vs[buf][tt][w * 4 + g];
            float2 dc = dbs[buf][tt];
            float2 cc = cs[buf][tt];

            // Q_t = d_{t-1}*W_{t-1} + C2[t-1]*delta_{t-1}   (scalar, slack-fed)
            float Qv = fmaf(dprev, Wprev, c2prev * dlprev);

            // delta (the only tight serial dependency)
            float delta = (vc - dc.x * P1) * dc.y;

            // W partials: k_{t+2} . S_{t-1}  (BEFORE the S update)
            float w0 = 0.f, w1 = 0.f, w2 = 0.f, w3 = 0.f;
#pragma unroll
            for (int i = 0; i < 16; i += 4) {
                w0 = fmaf(kn2[i],   S[i],   w0);
                w1 = fmaf(kn2[i+1], S[i+1], w1);
                w2 = fmaf(kn2[i+2], S[i+2], w2);
                w3 = fmaf(kn2[i+3], S[i+3], w3);
            }
            float Wp = (w0 + w1) + (w2 + w3);
            Wp += __shfl_xor_sync(0xffffffffu, Wp, 1);
            Wp += __shfl_xor_sync(0xffffffffu, Wp, 2);
            Wp += __shfl_xor_sync(0xffffffffu, Wp, 4);

            // S = d*S + k_t*delta ; o = q_t . S
            float b0 = 0.f, b1 = 0.f, b2 = 0.f, b3 = 0.f;
#pragma unroll
            for (int i = 0; i < 16; i += 4) {
                S[i]   = fmaf(S[i],   dc.x, kc[i]   * delta);
                S[i+1] = fmaf(S[i+1], dc.x, kc[i+1] * delta);
                S[i+2] = fmaf(S[i+2], dc.x, kc[i+2] * delta);
                S[i+3] = fmaf(S[i+3], dc.x, kc[i+3] * delta);
                b0 = fmaf(qc[i],   S[i],   b0);
                b1 = fmaf(qc[i+1], S[i+1], b1);
                b2 = fmaf(qc[i+2], S[i+2], b2);
                b3 = fmaf(qc[i+3], S[i+3], b3);
            }
            float ov = (b0 + b1) + (b2 + b3);
            ov += __shfl_xor_sync(0xffffffffu, ov, 1);
            ov += __shfl_xor_sync(0xffffffffu, ov, 2);
            ov += __shfl_xor_sync(0xffffffffu, ov, 4);
            if (s == 0) ob[(size_t)tt * VAL_DIM] = ov;

            // P1_{t+1} = d_t*Q_t + C1[t]*delta_t
            P1 = fmaf(dc.x, Qv, cc.x * delta);

            // carry state
            Wprev = Wp; dprev = dc.x; dlprev = delta; c2prev = cc.y;
#pragma unroll
            for (int i = 0; i < 16; i++) { kc[i] = kn[i]; kn[i] = kn2[i]; }
        }
        __syncthreads();
        buf ^= 1;
    }
}

// ---------------- gated RMS norm (emits fp16 og) ---------------------------
__global__ __launch_bounds__(128) void gnorm_kernel(
    const float* __restrict__ o, const float* __restrict__ gate,
    const float* __restrict__ w_norm, __half* __restrict__ og)
{
    int t = blockIdx.x >> 4;
    int h = blockIdx.x & 15;
    int c = threadIdx.x;
    size_t idx = (size_t)t * VAL_DIM + h * DV + c;
    float gt = gate[idx];
    float y = o[idx] * (gt / (1.f + expf(-gt)));
    float ss = y * y;
#pragma unroll
    for (int off = 16; off; off >>= 1) ss += __shfl_xor_sync(0xffffffffu, ss, off);
    __shared__ float wss[4];
    if ((threadIdx.x & 31) == 0) wss[threadIdx.x >> 5] = ss;
    __syncthreads();
    float mean = (wss[0] + wss[1] + wss[2] + wss[3]) * (1.f / DV);
    og[idx] = __float2half_rn(y * rsqrtf(mean + EPS_) * w_norm[c]);
}

// ---------------- launch ---------------------------------------------------
extern "C" void kernel_launch(void* const* d_in, const int* in_sizes, int n_in,
                              void* d_out, int out_size)
{
    const float* x      = (const float*)d_in[0];
    const float* Wq     = (const float*)d_in[1];
    const float* Wk     = (const float*)d_in[2];
    const float* Wv     = (const float*)d_in[3];
    const float* Wa     = (const float*)d_in[4];
    const float* Wb     = (const float*)d_in[5];
    const float* Wg     = (const float*)d_in[6];
    const float* Wo     = (const float*)d_in[7];
    const float* conv_q = (const float*)d_in[8];
    const float* conv_k = (const float*)d_in[9];
    const float* conv_v = (const float*)d_in[10];
    const float* A_log  = (const float*)d_in[11];
    const float* dt_b   = (const float*)d_in[12];
    const float* w_norm = (const float*)d_in[13];

    void* wsp = nullptr;
    cudaGetSymbolAddress(&wsp, g_ws_gdn);
    float* ws = (float*)wsp;
    float* qpre = ws + OF_QPRE;
    float* kpre = ws + OF_KPRE;
    float* vpre = ws + OF_VPRE;
    float* gate = ws + OF_GATE;
    float* qn   = ws + OF_QN;
    float* kn   = ws + OF_KN;
    float* vn   = ws + OF_VN;
    float2* db  = (float2*)(ws + OF_DB);
    float2* Cq  = (float2*)(ws + OF_CQ);
    float* o    = ws + OF_O;
    __half* xh  = (__half*)(ws + OF_XH);
    __half* wqh = (__half*)(ws + OF_WQH);
    __half* wkh = (__half*)(ws + OF_WKH);
    __half* wvh = (__half*)(ws + OF_WVH);
    __half* wgh = (__half*)(ws + OF_WGH);
    __half* woh = (__half*)(ws + OF_WOH);
    __half* ogh = (__half*)(ws + OF_OGH);
    float* out  = (float*)d_out;

    cudaFuncSetAttribute(gemm_x4, cudaFuncAttributeMaxDynamicSharedMemorySize, GDYN_SMEM);
    cudaFuncSetAttribute(gemm_h,  cudaFuncAttributeMaxDynamicSharedMemorySize, GDYN_SMEM);

    cvt_h_kernel<<<(int)(SZ_X   / 2048), 256>>>(x,  xh,  (int)SZ_X);
    cvt_h_kernel<<<(int)(SZ_WQK / 2048), 256>>>(Wq, wqh, (int)SZ_WQK);
    cvt_h_kernel<<<(int)(SZ_WQK / 2048), 256>>>(Wk, wkh, (int)SZ_WQK);
    cvt_h_kernel<<<(int)(SZ_WV  / 2048), 256>>>(Wv, wvh, (int)SZ_WV);
    cvt_h_kernel<<<(int)(SZ_WV  / 2048), 256>>>(Wg, wgh, (int)SZ_WV);
    cvt_h_kernel<<<(int)(SZ_WV  / 2048), 256>>>(Wo, woh, (int)SZ_WV);

    dim3 blk(256);
    dim3 g_x4(48, S_LEN / GBM);
    dim3 g_o (VAL_DIM / GBN, S_LEN / GBM);

    gemm_x4<<<g_x4, blk, GDYN_SMEM>>>(xh, wqh, wkh, wvh, wgh, qpre, kpre, vpre, gate);
    gemv_ab<<<S_LEN / 8, 128>>>(x, Wa, Wb, A_log, dt_b, db);

    convqk_kernel<<<S_LEN * NH, 128>>>(qpre, conv_q, qn, SCALE_);
    convqk_kernel<<<S_LEN * NH, 128>>>(kpre, conv_k, kn, 1.f);
    convv_kernel<<<(S_LEN * VAL_DIM) / 256, 256>>>(vpre, conv_v, vn);
    dotck_kernel<<<S_LEN * NH / 8, 256>>>(kn, Cq);

    scan_kernel<<<128, 128>>>(kn, qn, vn, db, Cq, o);

    gnorm_kernel<<<S_LEN * NVH, 128>>>(o, gate, w_norm, ogh);

    gemm_h<<<g_o, blk, GDYN_SMEM>>>(ogh, woh, out, HID, VAL_DIM);
}

// round 14
// speedup vs baseline: 1.0749x; 1.0749x over previous
#include <cuda_runtime.h>
#include <cuda_fp16.h>
#include <math.h>
#include <stdint.h>

// ---------------- problem constants ----------------
#define S_LEN 4096
#define HID   2048
#define NH    8
#define NVH   16
#define DK    128
#define DV    128
#define KEY_DIM  (NH*DK)    // 1024
#define VAL_DIM  (NVH*DV)   // 2048
#define CONV  4
#define EPS_  1e-6f
#define SCALE_ 0.08838834764831845f   // 128^-0.5

// ---------------- workspace -------------------------------------------------
static constexpr size_t SZ_QPRE = (size_t)S_LEN * KEY_DIM;
static constexpr size_t SZ_VPRE = (size_t)S_LEN * VAL_DIM;
static constexpr size_t SZ_AB   = (size_t)S_LEN * NVH;
static constexpr size_t SZ_C    = (size_t)S_LEN * NH;
static constexpr size_t SZ_X    = (size_t)S_LEN * HID;
static constexpr size_t SZ_WQK  = (size_t)KEY_DIM * HID;
static constexpr size_t SZ_WV   = (size_t)VAL_DIM * HID;

static constexpr size_t OF_QPRE = 0;
static constexpr size_t OF_KPRE = OF_QPRE + SZ_QPRE;
static constexpr size_t OF_VPRE = OF_KPRE + SZ_QPRE;
static constexpr size_t OF_GATE = OF_VPRE + SZ_VPRE;
static constexpr size_t OF_QN   = OF_GATE + SZ_VPRE;
static constexpr size_t OF_KN   = OF_QN + SZ_QPRE;
static constexpr size_t OF_VN   = OF_KN + SZ_QPRE;
static constexpr size_t OF_DB   = OF_VN + SZ_VPRE;   // float2 per (t,h)
static constexpr size_t OF_CQ   = OF_DB + 2*SZ_AB;   // C1 per (t,hk)
static constexpr size_t OF_O    = OF_CQ + SZ_C;
// fp16 buffers (element counts halved into float units)
static constexpr size_t OF_XH   = OF_O + SZ_VPRE;
static constexpr size_t OF_WQH  = OF_XH + SZ_X/2;
static constexpr size_t OF_WKH  = OF_WQH + SZ_WQK/2;
static constexpr size_t OF_WVH  = OF_WKH + SZ_WQK/2;
static constexpr size_t OF_WGH  = OF_WVH + SZ_WV/2;
static constexpr size_t OF_WOH  = OF_WGH + SZ_WV/2;
static constexpr size_t OF_OGH  = OF_WOH + SZ_WV/2;
static constexpr size_t WS_TOTAL = OF_OGH + SZ_VPRE/2;

__device__ float g_ws_gdn[WS_TOTAL];

// ---------------- cp.async helpers -----------------------------------------
__device__ __forceinline__ void cp16(void* s, const void* g) {
    asm volatile("cp.async.ca.shared.global [%0], [%1], 16;"
                 :: "r"((uint32_t)__cvta_generic_to_shared(s)), "l"(g));
}
__device__ __forceinline__ void cp8(void* s, const void* g) {
    asm volatile("cp.async.ca.shared.global [%0], [%1], 8;"
                 :: "r"((uint32_t)__cvta_generic_to_shared(s)), "l"(g));
}
__device__ __forceinline__ void cp4(void* s, const void* g) {
    asm volatile("cp.async.ca.shared.global [%0], [%1], 4;"
                 :: "r"((uint32_t)__cvta_generic_to_shared(s)), "l"(g));
}
__device__ __forceinline__ void cp_commit() {
    asm volatile("cp.async.commit_group;");
}

// ---------------- fp32 -> fp16 conversion ----------------------------------
__global__ __launch_bounds__(256) void cvt_h_kernel(
    const float* __restrict__ in, __half* __restrict__ out, int n)
{
    int i = (blockIdx.x * 256 + threadIdx.x) * 8;
    if (i >= n) return;
    float4 v0 = *(const float4*)(in + i);
    float4 v1 = *(const float4*)(in + i + 4);
    __half2 h[4];
    h[0] = __floats2half2_rn(v0.x, v0.y);
    h[1] = __floats2half2_rn(v0.z, v0.w);
    h[2] = __floats2half2_rn(v1.x, v1.y);
    h[3] = __floats2half2_rn(v1.z, v1.w);
    *(uint4*)(out + i) = *(uint4*)h;
}

// ================= fp16 tensor-core GEMM (k32 stages, 4-deep ring) =========
#define GBM 128
#define GBN 128
#define KC  32
#define PADH 40
#define STAGE_H (2 * GBM * PADH)
#define GDYN_SMEM (4 * STAGE_H * 2)    // 81920 bytes

__device__ __forceinline__ void mma_f16(float* c, const uint32_t* a, const uint32_t* b) {
    asm volatile(
        "mma.sync.aligned.m16n8k16.row.col.f32.f16.f16.f32 "
        "{%0,%1,%2,%3}, {%4,%5,%6,%7}, {%8,%9}, {%0,%1,%2,%3};"
        : "+f"(c[0]), "+f"(c[1]), "+f"(c[2]), "+f"(c[3])
        : "r"(a[0]), "r"(a[1]), "r"(a[2]), "r"(a[3]), "r"(b[0]), "r"(b[1]));
}

__device__ __forceinline__ void ldsm4(uint32_t* r, uint32_t addr) {
    asm volatile("ldmatrix.sync.aligned.m8n8.x4.shared.b16 {%0,%1,%2,%3}, [%4];"
                 : "=r"(r[0]), "=r"(r[1]), "=r"(r[2]), "=r"(r[3]) : "r"(addr));
}

__device__ __forceinline__ void gemm_core(
    const __half* __restrict__ A, const __half* __restrict__ B,
    float* __restrict__ C, int n0, int ldc, int K)
{
    extern __shared__ __half smh[];
    uint32_t sbase = (uint32_t)__cvta_generic_to_shared(smh);

    int tid = threadIdx.x;
    int warp = tid >> 5;
    int lane = tid & 31;
    int gid = lane >> 2;
    int tig = lane & 3;

    int m0 = blockIdx.y * GBM;
    int wm = (warp >> 2) * 64;
    int wn = (warp & 3) * 32;

    int lrow = tid >> 1;
    int lk   = (tid & 1) * 16;
    const __half* Ag = A + (size_t)(m0 + lrow) * K + lk;
    const __half* Bg = B + (size_t)(n0 + lrow) * K + lk;
    int sA = lrow * PADH + lk;
    int sB = GBM * PADH + lrow * PADH + lk;

    int arow = wm + (lane & 15);
    int akh  = (lane >> 4) * 8;
    int brow = wn + (lane & 7) + ((lane >> 4) << 3);
    int bkh  = ((lane >> 3) & 1) * 8;

    float acc[4][4][4];
#pragma unroll
    for (int i = 0; i < 4; i++)
#pragma unroll
        for (int j = 0; j < 4; j++)
#pragma unroll
            for (int r = 0; r < 4; r++) acc[i][j][r] = 0.f;

    int kIters = K / KC;

#pragma unroll
    for (int s = 0; s < 3; s++) {
        __half* stg = smh + s * STAGE_H;
        cp16(stg + sA,     Ag + (size_t)s * KC);
        cp16(stg + sA + 8, Ag + (size_t)s * KC + 8);
        cp16(stg + sB,     Bg + (size_t)s * KC);
        cp16(stg + sB + 8, Bg + (size_t)s * KC + 8);
        cp_commit();
    }

    for (int it = 0; it < kIters; it++) {
        asm volatile("cp.async.wait_group 2;");
        __syncthreads();

        if (it + 3 < kIters) {
            __half* stg = smh + ((it + 3) & 3) * STAGE_H;
            cp16(stg + sA,     Ag + (size_t)(it + 3) * KC);
            cp16(stg + sA + 8, Ag + (size_t)(it + 3) * KC + 8);
            cp16(stg + sB,     Bg + (size_t)(it + 3) * KC);
            cp16(stg + sB + 8, Bg + (size_t)(it + 3) * KC + 8);
        }
        cp_commit();

        uint32_t stg = sbase + ((it & 3) * STAGE_H) * 2;

#pragma unroll
        for (int sub = 0; sub < 2; sub++) {
            int cb = sub * 16;
            uint32_t aaddr = stg + (uint32_t)(arow * PADH + cb + akh) * 2;
            uint32_t baddr = stg + (uint32_t)(GBM * PADH + brow * PADH + cb + bkh) * 2;

            uint32_t af[4][4], bfr[2][4];
#pragma unroll
            for (int mt = 0; mt < 4; mt++) ldsm4(af[mt], aaddr + mt * 16 * PADH * 2);
#pragma unroll
            for (int pt = 0; pt < 2; pt++) ldsm4(bfr[pt], baddr + pt * 16 * PADH * 2);

#pragma unroll
            for (int mt = 0; mt < 4; mt++)
#pragma unroll
                for (int nt = 0; nt < 4; nt++)
                    mma_f16(acc[mt][nt], af[mt], &bfr[nt >> 1][(nt & 1) * 2]);
        }
    }

#pragma unroll
    for (int mt = 0; mt < 4; mt++) {
#pragma unroll
        for (int nt = 0; nt < 4; nt++) {
            int m = m0 + wm + mt * 16 + gid;
            int n = n0 + wn + nt * 8 + tig * 2;
            *(float2*)&C[(size_t)m * ldc + n] = make_float2(acc[mt][nt][0], acc[mt][nt][1]);
            *(float2*)&C[(size_t)(m + 8) * ldc + n] = make_float2(acc[mt][nt][2], acc[mt][nt][3]);
        }
    }
}

// merged x-projection: blockIdx.x 0..7 Wq, 8..15 Wk, 16..31 Wv, 32..47 Wg
__global__ __launch_bounds__(256, 2) void gemm_x4(
    const __half* __restrict__ x,
    const __half* __restrict__ Wq, const __half* __restrict__ Wk,
    const __half* __restrict__ Wv, const __half* __restrict__ Wg,
    float* __restrict__ qpre, float* __restrict__ kpre,
    float* __restrict__ vpre, float* __restrict__ gate)
{
    int bx = blockIdx.x;
    const __half* B; float* C; int n0; int ldc;
    if (bx < 8)       { B = Wq; C = qpre; n0 = bx * 128;        ldc = KEY_DIM; }
    else if (bx < 16) { B = Wk; C = kpre; n0 = (bx - 8) * 128;  ldc = KEY_DIM; }
    else if (bx < 32) { B = Wv; C = vpre; n0 = (bx - 16) * 128; ldc = VAL_DIM; }
    else              { B = Wg; C = gate; n0 = (bx - 32) * 128; ldc = VAL_DIM; }
    gemm_core(x, B, C, n0, ldc, HID);
}

__global__ __launch_bounds__(256, 2) void gemm_h(
    const __half* __restrict__ A, const __half* __restrict__ B,
    float* __restrict__ C, int N, int K)
{
    gemm_core(A, B, C, blockIdx.x * GBN, N, K);
}

// ---------------- fused a/b projection + decay/beta -----------------------
__global__ __launch_bounds__(128) void gemv_ab(
    const float* __restrict__ x, const float* __restrict__ Wa,
    const float* __restrict__ Wb, const float* __restrict__ A_log,
    const float* __restrict__ dt_bias, float2* __restrict__ db)
{
    __shared__ float xs[8][260];
    __shared__ float was[16][260];
    __shared__ float wbs[16][260];

    int tid = threadIdx.x;
    int row = tid >> 4, n = tid & 15;
    int r0 = blockIdx.x * 8;

    float acc_a = 0.f, acc_b = 0.f;
    for (int kc = 0; kc < HID; kc += 256) {
        __syncthreads();
        int lr = tid >> 4, lo = (tid & 15) * 16;
#pragma unroll
        for (int j = 0; j < 16; j += 4)
            *(float4*)&xs[lr][lo + j] = *(const float4*)&x[(size_t)(r0 + lr) * HID + kc + lo + j];
        int wr = tid >> 3, wo = (tid & 7) * 32;
#pragma unroll
        for (int j = 0; j < 32; j += 4) {
            *(float4*)&was[wr][wo + j] = *(const float4*)&Wa[(size_t)wr * HID + kc + wo + j];
            *(float4*)&wbs[wr][wo + j] = *(const float4*)&Wb[(size_t)wr * HID + kc + wo + j];
        }
        __syncthreads();
#pragma unroll 8
        for (int j = 0; j < 256; j += 4) {
            float4 xv = *(float4*)&xs[row][j];
            float4 wa = *(float4*)&was[n][j];
            float4 wb = *(float4*)&wbs[n][j];
            acc_a += xv.x*wa.x + xv.y*wa.y + xv.z*wa.z + xv.w*wa.w;
            acc_b += xv.x*wb.x + xv.y*wb.y + xv.z*wb.z + xv.w*wb.w;
        }
    }
    float a = acc_a + dt_bias[n];
    float sp = (a > 20.f) ? a : log1pf(expf(a));
    float decay = expf(-expf(A_log[n]) * sp);
    float beta = 1.f / (1.f + expf(-acc_b));
    db[(size_t)(r0 + row) * NVH + n] = make_float2(decay, beta);
}

// ---------------- conv + silu + l2norm for q/k ----------------------------
__global__ __launch_bounds__(128) void convqk_kernel(
    const float* __restrict__ pre, const float* __restrict__ cw,
    float* __restrict__ out, float scale)
{
    int t = blockIdx.x >> 3;
    int h = blockIdx.x & 7;
    int c = threadIdx.x;
    int ch = h * DK + c;
    float y = 0.f;
#pragma unroll
    for (int j = 0; j < CONV; j++) {
        int tt = t - (CONV-1) + j;
        float xv = (tt >= 0) ? pre[(size_t)tt * KEY_DIM + ch] : 0.f;
        y = fmaf(xv, cw[ch*CONV + j], y);
    }
    y = y / (1.f + expf(-y));
    float ss = y * y;
#pragma unroll
    for (int off = 16; off; off >>= 1) ss += __shfl_xor_sync(0xffffffffu, ss, off);
    __shared__ float wss[4];
    if ((threadIdx.x & 31) == 0) wss[threadIdx.x >> 5] = ss;
    __syncthreads();
    float tot = wss[0] + wss[1] + wss[2] + wss[3];
    out[(size_t)t * KEY_DIM + ch] = y * rsqrtf(tot + EPS_) * scale;
}

// ---------------- conv + silu for v ---------------------------------------
__global__ __launch_bounds__(256) void convv_kernel(
    const float* __restrict__ pre, const float* __restrict__ cw,
    float* __restrict__ out)
{
    int idx = blockIdx.x * blockDim.x + threadIdx.x;
    int t = idx >> 11;
    int ch = idx & 2047;
    float y = 0.f;
#pragma unroll
    for (int j = 0; j < CONV; j++) {
        int tt = t - (CONV-1) + j;
        float xv = (tt >= 0) ? pre[(size_t)tt * VAL_DIM + ch] : 0.f;
        y = fmaf(xv, cw[ch*CONV + j], y);
    }
    out[idx] = y / (1.f + expf(-y));
}

// ---------------- C[t][hk] = k_{t+1} . k_t per key head --------------------
__global__ __launch_bounds__(256) void dotck_kernel(
    const float* __restrict__ k, float* __restrict__ Cq)
{
    int warp = threadIdx.x >> 5;
    int lane = threadIdx.x & 31;
    int idx = blockIdx.x * 8 + warp;       // t*NH + hk
    int t = idx >> 3, hk = idx & 7;
    float cv = 0.f;
    if (t + 1 < S_LEN) {
        const float* k0 = k + (size_t)t * KEY_DIM + hk * DK + lane * 4;
        const float* k1 = k0 + KEY_DIM;
        float4 a = *(const float4*)k0;
        float4 b = *(const float4*)k1;
        cv = a.x*b.x + a.y*b.y + a.z*b.z + a.w*b.w;
#pragma unroll
        for (int off = 16; off; off >>= 1) cv += __shfl_xor_sync(0xffffffffu, cv, off);
    }
    if (lane == 0) Cq[(size_t)t * NH + hk] = cv;
}

// ---------------- delta-rule scan v7: 16-lane groups, 2 warps/SMSP ---------
// 128 blocks x 256 threads. Warp w owns 2 columns (g = lane>>4); 16 lanes per
// column, 8 state floats per lane. Algebra = v5 (one-step lookahead via C1).
#define CH 16
#define KST 140   // 17 rows * 8 + 4 ; (140/4)=35 odd -> bank spread OK
#define QST 132   // 16 rows * 8 + 4 ; 33 odd

__global__ __launch_bounds__(256) void scan_kernel(
    const float* __restrict__ k, const float* __restrict__ q,
    const float* __restrict__ v, const float2* __restrict__ db,
    const float* __restrict__ Cq, float* __restrict__ o)
{
    __shared__ float ksw[2][16 * KST];
    __shared__ float qsw[2][16 * QST];
    __shared__ float vs[2][CH][16];
    __shared__ float2 dbs[2][CH];
    __shared__ float cs[2][CH];

    int h = blockIdx.x >> 3;
    int hk = h >> 1;
    int colbase = (blockIdx.x & 7) * 16;
    int tid = threadIdx.x;
    int w = tid >> 5, lane = tid & 31;
    int g = lane >> 4;              // 0..1 column within warp
    int s = lane & 15;              // reduce-lane within column
    int col = colbase + w * 2 + g;

    // producer mapping: row plr (0..15), group pgp (0..15), 8 floats each
    int plr = tid >> 4;
    int pgp = tid & 15;
    int vr = tid >> 2;              // 0..63 (tid<64)

    const float* kbase = k + hk * DK;
    const float* qbase = q + hk * DK;
    const float* vbase = v + h * DV + colbase + (tid & 3) * 4;
    const float2* dbase = db + h;
    const float* cbase = Cq + hk;
    float* obase = o + h * DV + col;

    // ---- issue chunk 0 ----
    {
        const float* krow = kbase + (size_t)plr * KEY_DIM + pgp * 8;
        const float* qrow = qbase + (size_t)plr * KEY_DIM + pgp * 8;
        cp16(&ksw[0][pgp * KST + plr * 8],     krow);
        cp16(&ksw[0][pgp * KST + plr * 8 + 4], krow + 4);
        cp16(&qsw[0][pgp * QST + plr * 8],     qrow);
        cp16(&qsw[0][pgp * QST + plr * 8 + 4], qrow + 4);
        if (tid < 16) {
            const float* kov = kbase + (size_t)CH * KEY_DIM + tid * 8;
            cp16(&ksw[0][tid * KST + CH * 8],     kov);
            cp16(&ksw[0][tid * KST + CH * 8 + 4], kov + 4);
        }
        if (tid < 64) cp16(&vs[0][vr][(tid & 3) * 4], vbase + (size_t)vr * VAL_DIM);
        if (tid < CH) cp8(&dbs[0][tid], dbase + (size_t)tid * NVH);
        if (tid < CH) cp4(&cs[0][tid], cbase + (size_t)tid * NH);
        cp_commit();
    }

    float S[8];
#pragma unroll
    for (int i = 0; i < 8; i++) S[i] = 0.f;
    float P1 = 0.f;
    float kc[8];
    bool kc_init = false;

    int buf = 0;
    const int NCH = S_LEN / CH;
    for (int c = 0; c < NCH; c++) {
        if (c + 1 < NCH) {
            int t0 = (c + 1) * CH;
            int p = buf ^ 1;
            const float* krow = kbase + (size_t)(t0 + plr) * KEY_DIM + pgp * 8;
            const float* qrow = qbase + (size_t)(t0 + plr) * KEY_DIM + pgp * 8;
            cp16(&ksw[p][pgp * KST + plr * 8],     krow);
            cp16(&ksw[p][pgp * KST + plr * 8 + 4], krow + 4);
            cp16(&qsw[p][pgp * QST + plr * 8],     qrow);
            cp16(&qsw[p][pgp * QST + plr * 8 + 4], qrow + 4);
            if (tid < 16) {
                int ovr = t0 + CH; if (ovr > S_LEN - 1) ovr = S_LEN - 1;
                const float* kov = kbase + (size_t)ovr * KEY_DIM + tid * 8;
                cp16(&ksw[p][tid * KST + CH * 8],     kov);
                cp16(&ksw[p][tid * KST + CH * 8 + 4], kov + 4);
            }
            if (tid < 64) cp16(&vs[p][vr][(tid & 3) * 4], vbase + (size_t)(t0 + vr) * VAL_DIM);
            if (tid < CH) cp8(&dbs[p][tid], dbase + (size_t)(t0 + tid) * NVH);
            if (tid < CH) cp4(&cs[p][tid], cbase + (size_t)(t0 + tid) * NH);
            cp_commit();
            asm volatile("cp.async.wait_group 1;");
        } else {
            asm volatile("cp.async.wait_group 0;");
        }
        __syncthreads();

        if (!kc_init) {
            *(float4*)&kc[0] = *(const float4*)&ksw[0][s * KST];
            *(float4*)&kc[4] = *(const float4*)&ksw[0][s * KST + 4];
            kc_init = true;
        }

        int t0 = c * CH;
        float* ob = obase + (size_t)t0 * VAL_DIM;
#pragma unroll
        for (int tt = 0; tt < CH; tt++) {
            float kn[8], qc[8];
            *(float4*)&kn[0] = *(const float4*)&ksw[buf][s * KST + (tt + 1) * 8];
            *(float4*)&kn[4] = *(const float4*)&ksw[buf][s * KST + (tt + 1) * 8 + 4];
            *(float4*)&qc[0] = *(const float4*)&qsw[buf][s * QST + tt * 8];
            *(float4*)&qc[4] = *(const float4*)&qsw[buf][s * QST + tt * 8 + 4];
            float vc = vs[buf][tt][w * 2 + g];
            float2 dc = dbs[buf][tt];
            float Ct = cs[buf][tt];

            // A = k_{t+1} . S_{t-1}
            float a0 = 0.f, a1 = 0.f;
#pragma unroll
            for (int i = 0; i < 8; i += 2) {
                a0 = fmaf(kn[i],   S[i],   a0);
                a1 = fmaf(kn[i+1], S[i+1], a1);
            }
            float A = a0 + a1;

            float delta = (vc - dc.x * P1) * dc.y;

            // S = d*S + k_t*delta ; o = q_t . S
            float b0 = 0.f, b1 = 0.f;
#pragma unroll
            for (int i = 0; i < 8; i += 2) {
                S[i]   = fmaf(S[i],   dc.x, kc[i]   * delta);
                S[i+1] = fmaf(S[i+1], dc.x, kc[i+1] * delta);
                b0 = fmaf(qc[i],   S[i],   b0);
                b1 = fmaf(qc[i+1], S[i+1], b1);
            }
            float ov = b0 + b1;

            A  += __shfl_xor_sync(0xffffffffu, A, 1);
            A  += __shfl_xor_sync(0xffffffffu, A, 2);
            A  += __shfl_xor_sync(0xffffffffu, A, 4);
            A  += __shfl_xor_sync(0xffffffffu, A, 8);
            ov += __shfl_xor_sync(0xffffffffu, ov, 1);
            ov += __shfl_xor_sync(0xffffffffu, ov, 2);
            ov += __shfl_xor_sync(0xffffffffu, ov, 4);
            ov += __shfl_xor_sync(0xffffffffu, ov, 8);
            if (s == 0) ob[(size_t)tt * VAL_DIM] = ov;

            P1 = fmaf(dc.x, A, Ct * delta);
#pragma unroll
            for (int i = 0; i < 8; i++) kc[i] = kn[i];
        }
        __syncthreads();
        buf ^= 1;
    }
}

// ---------------- gated RMS norm (emits fp16 og) ---------------------------
__global__ __launch_bounds__(128) void gnorm_kernel(
    const float* __restrict__ o, const float* __restrict__ gate,
    const float* __restrict__ w_norm, __half* __restrict__ og)
{
    int t = blockIdx.x >> 4;
    int h = blockIdx.x & 15;
    int c = threadIdx.x;
    size_t idx = (size_t)t * VAL_DIM + h * DV + c;
    float gt = gate[idx];
    float y = o[idx] * (gt / (1.f + expf(-gt)));
    float ss = y * y;
#pragma unroll
    for (int off = 16; off; off >>= 1) ss += __shfl_xor_sync(0xffffffffu, ss, off);
    __shared__ float wss[4];
    if ((threadIdx.x & 31) == 0) wss[threadIdx.x >> 5] = ss;
    __syncthreads();
    float mean = (wss[0] + wss[1] + wss[2] + wss[3]) * (1.f / DV);
    og[idx] = __float2half_rn(y * rsqrtf(mean + EPS_) * w_norm[c]);
}

// ---------------- launch ---------------------------------------------------
extern "C" void kernel_launch(void* const* d_in, const int* in_sizes, int n_in,
                              void* d_out, int out_size)
{
    const float* x      = (const float*)d_in[0];
    const float* Wq     = (const float*)d_in[1];
    const float* Wk     = (const float*)d_in[2];
    const float* Wv     = (const float*)d_in[3];
    const float* Wa     = (const float*)d_in[4];
    const float* Wb     = (const float*)d_in[5];
    const float* Wg     = (const float*)d_in[6];
    const float* Wo     = (const float*)d_in[7];
    const float* conv_q = (const float*)d_in[8];
    const float* conv_k = (const float*)d_in[9];
    const float* conv_v = (const float*)d_in[10];
    const float* A_log  = (const float*)d_in[11];
    const float* dt_b   = (const float*)d_in[12];
    const float* w_norm = (const float*)d_in[13];

    void* wsp = nullptr;
    cudaGetSymbolAddress(&wsp, g_ws_gdn);
    float* ws = (float*)wsp;
    float* qpre = ws + OF_QPRE;
    float* kpre = ws + OF_KPRE;
    float* vpre = ws + OF_VPRE;
    float* gate = ws + OF_GATE;
    float* qn   = ws + OF_QN;
    float* kn   = ws + OF_KN;
    float* vn   = ws + OF_VN;
    float2* db  = (float2*)(ws + OF_DB);
    float* Cq   = ws + OF_CQ;
    float* o    = ws + OF_O;
    __half* xh  = (__half*)(ws + OF_XH);
    __half* wqh = (__half*)(ws + OF_WQH);
    __half* wkh = (__half*)(ws + OF_WKH);
    __half* wvh = (__half*)(ws + OF_WVH);
    __half* wgh = (__half*)(ws + OF_WGH);
    __half* woh = (__half*)(ws + OF_WOH);
    __half* ogh = (__half*)(ws + OF_OGH);
    float* out  = (float*)d_out;

    cudaFuncSetAttribute(gemm_x4, cudaFuncAttributeMaxDynamicSharedMemorySize, GDYN_SMEM);
    cudaFuncSetAttribute(gemm_h,  cudaFuncAttributeMaxDynamicSharedMemorySize, GDYN_SMEM);

    cvt_h_kernel<<<(int)(SZ_X   / 2048), 256>>>(x,  xh,  (int)SZ_X);
    cvt_h_kernel<<<(int)(SZ_WQK / 2048), 256>>>(Wq, wqh, (int)SZ_WQK);
    cvt_h_kernel<<<(int)(SZ_WQK / 2048), 256>>>(Wk, wkh, (int)SZ_WQK);
    cvt_h_kernel<<<(int)(SZ_WV  / 2048), 256>>>(Wv, wvh, (int)SZ_WV);
    cvt_h_kernel<<<(int)(SZ_WV  / 2048), 256>>>(Wg, wgh, (int)SZ_WV);
    cvt_h_kernel<<<(int)(SZ_WV  / 2048), 256>>>(Wo, woh, (int)SZ_WV);

    dim3 blk(256);
    dim3 g_x4(48, S_LEN / GBM);
    dim3 g_o (VAL_DIM / GBN, S_LEN / GBM);

    gemm_x4<<<g_x4, blk, GDYN_SMEM>>>(xh, wqh, wkh, wvh, wgh, qpre, kpre, vpre, gate);
    gemv_ab<<<S_LEN / 8, 128>>>(x, Wa, Wb, A_log, dt_b, db);

    convqk_kernel<<<S_LEN * NH, 128>>>(qpre, conv_q, qn, SCALE_);
    convqk_kernel<<<S_LEN * NH, 128>>>(kpre, conv_k, kn, 1.f);
    convv_kernel<<<(S_LEN * VAL_DIM) / 256, 256>>>(vpre, conv_v, vn);
    dotck_kernel<<<S_LEN * NH / 8, 256>>>(kn, Cq);

    scan_kernel<<<128, 256>>>(kn, qn, vn, db, Cq, o);

    gnorm_kernel<<<S_LEN * NVH, 128>>>(o, gate, w_norm, ogh);

    gemm_h<<<g_o, blk, GDYN_SMEM>>>(ogh, woh, out, HID, VAL_DIM);
}

// round 15
// speedup vs baseline: 1.0965x; 1.0201x over previous
#include <cuda_runtime.h>
#include <cuda_fp16.h>
#include <math.h>
#include <stdint.h>

// ---------------- problem constants ----------------
#define S_LEN 4096
#define HID   2048
#define NH    8
#define NVH   16
#define DK    128
#define DV    128
#define KEY_DIM  (NH*DK)    // 1024
#define VAL_DIM  (NVH*DV)   // 2048
#define CONV  4
#define EPS_  1e-6f
#define SCALE_ 0.08838834764831845f   // 128^-0.5

// ---------------- workspace -------------------------------------------------
static constexpr size_t SZ_QPRE = (size_t)S_LEN * KEY_DIM;
static constexpr size_t SZ_VPRE = (size_t)S_LEN * VAL_DIM;
static constexpr size_t SZ_AB   = (size_t)S_LEN * NVH;
static constexpr size_t SZ_C    = (size_t)S_LEN * NH;
static constexpr size_t SZ_X    = (size_t)S_LEN * HID;
static constexpr size_t SZ_WQK  = (size_t)KEY_DIM * HID;
static constexpr size_t SZ_WV   = (size_t)VAL_DIM * HID;

static constexpr size_t OF_QPRE = 0;
static constexpr size_t OF_KPRE = OF_QPRE + SZ_QPRE;
static constexpr size_t OF_VPRE = OF_KPRE + SZ_QPRE;
static constexpr size_t OF_GATE = OF_VPRE + SZ_VPRE;
static constexpr size_t OF_QN   = OF_GATE + SZ_VPRE;
static constexpr size_t OF_KN   = OF_QN + SZ_QPRE;
static constexpr size_t OF_VN   = OF_KN + SZ_QPRE;
static constexpr size_t OF_DB   = OF_VN + SZ_VPRE;   // float2 per (t,h)
static constexpr size_t OF_CQ   = OF_DB + 2*SZ_AB;   // C1 per (t,hk)
static constexpr size_t OF_O    = OF_CQ + SZ_C;
// fp16 buffers (element counts halved into float units) -- CONTIGUOUS
static constexpr size_t OF_XH   = OF_O + SZ_VPRE;
static constexpr size_t OF_WQH  = OF_XH + SZ_X/2;
static constexpr size_t OF_WKH  = OF_WQH + SZ_WQK/2;
static constexpr size_t OF_WVH  = OF_WKH + SZ_WQK/2;
static constexpr size_t OF_WGH  = OF_WVH + SZ_WV/2;
static constexpr size_t OF_WOH  = OF_WGH + SZ_WV/2;
static constexpr size_t OF_OGH  = OF_WOH + SZ_WV/2;
static constexpr size_t WS_TOTAL = OF_OGH + SZ_VPRE/2;

__device__ float g_ws_gdn[WS_TOTAL];

// ---------------- cp.async helpers -----------------------------------------
__device__ __forceinline__ void cp16(void* s, const void* g) {
    asm volatile("cp.async.ca.shared.global [%0], [%1], 16;"
                 :: "r"((uint32_t)__cvta_generic_to_shared(s)), "l"(g));
}
__device__ __forceinline__ void cp8(void* s, const void* g) {
    asm volatile("cp.async.ca.shared.global [%0], [%1], 8;"
                 :: "r"((uint32_t)__cvta_generic_to_shared(s)), "l"(g));
}
__device__ __forceinline__ void cp4(void* s, const void* g) {
    asm volatile("cp.async.ca.shared.global [%0], [%1], 4;"
                 :: "r"((uint32_t)__cvta_generic_to_shared(s)), "l"(g));
}
__device__ __forceinline__ void cp_commit() {
    asm volatile("cp.async.commit_group;");
}

// ---------------- fused fp32 -> fp16 conversion (all 6 tensors) ------------
// Destinations are contiguous starting at xh; sources segment by element idx.
__global__ __launch_bounds__(256) void cvt_all_kernel(
    const float* __restrict__ x,
    const float* __restrict__ Wq, const float* __restrict__ Wk,
    const float* __restrict__ Wv, const float* __restrict__ Wg,
    const float* __restrict__ Wo, __half* __restrict__ out)
{
    const size_t B0 = SZ_X;
    const size_t B1 = B0 + SZ_WQK;
    const size_t B2 = B1 + SZ_WQK;
    const size_t B3 = B2 + SZ_WV;
    const size_t B4 = B3 + SZ_WV;
    const size_t B5 = B4 + SZ_WV;
    size_t i = ((size_t)blockIdx.x * 256 + threadIdx.x) * 8;
    if (i >= B5) return;
    const float* src; size_t off;
    if (i < B0)      { src = x;  off = i; }
    else if (i < B1) { src = Wq; off = i - B0; }
    else if (i < B2) { src = Wk; off = i - B1; }
    else if (i < B3) { src = Wv; off = i - B2; }
    else if (i < B4) { src = Wg; off = i - B3; }
    else             { src = Wo; off = i - B4; }
    float4 v0 = *(const float4*)(src + off);
    float4 v1 = *(const float4*)(src + off + 4);
    __half2 h[4];
    h[0] = __floats2half2_rn(v0.x, v0.y);
    h[1] = __floats2half2_rn(v0.z, v0.w);
    h[2] = __floats2half2_rn(v1.x, v1.y);
    h[3] = __floats2half2_rn(v1.z, v1.w);
    *(uint4*)(out + i) = *(uint4*)h;
}

// ================= fp16 tensor-core GEMM (k32 stages, 4-deep ring) =========
#define GBM 128
#define GBN 128
#define KC  32
#define PADH 40
#define STAGE_H (2 * GBM * PADH)
#define GDYN_SMEM (4 * STAGE_H * 2)    // 81920 bytes

__device__ __forceinline__ void mma_f16(float* c, const uint32_t* a, const uint32_t* b) {
    asm volatile(
        "mma.sync.aligned.m16n8k16.row.col.f32.f16.f16.f32 "
        "{%0,%1,%2,%3}, {%4,%5,%6,%7}, {%8,%9}, {%0,%1,%2,%3};"
        : "+f"(c[0]), "+f"(c[1]), "+f"(c[2]), "+f"(c[3])
        : "r"(a[0]), "r"(a[1]), "r"(a[2]), "r"(a[3]), "r"(b[0]), "r"(b[1]));
}

__device__ __forceinline__ void ldsm4(uint32_t* r, uint32_t addr) {
    asm volatile("ldmatrix.sync.aligned.m8n8.x4.shared.b16 {%0,%1,%2,%3}, [%4];"
                 : "=r"(r[0]), "=r"(r[1]), "=r"(r[2]), "=r"(r[3]) : "r"(addr));
}

__device__ __forceinline__ void gemm_core(
    const __half* __restrict__ A, const __half* __restrict__ B,
    float* __restrict__ C, int n0, int ldc, int K)
{
    extern __shared__ __half smh[];
    uint32_t sbase = (uint32_t)__cvta_generic_to_shared(smh);

    int tid = threadIdx.x;
    int warp = tid >> 5;
    int lane = tid & 31;
    int gid = lane >> 2;
    int tig = lane & 3;

    int m0 = blockIdx.y * GBM;
    int wm = (warp >> 2) * 64;
    int wn = (warp & 3) * 32;

    int lrow = tid >> 1;
    int lk   = (tid & 1) * 16;
    const __half* Ag = A + (size_t)(m0 + lrow) * K + lk;
    const __half* Bg = B + (size_t)(n0 + lrow) * K + lk;
    int sA = lrow * PADH + lk;
    int sB = GBM * PADH + lrow * PADH + lk;

    int arow = wm + (lane & 15);
    int akh  = (lane >> 4) * 8;
    int brow = wn + (lane & 7) + ((lane >> 4) << 3);
    int bkh  = ((lane >> 3) & 1) * 8;

    float acc[4][4][4];
#pragma unroll
    for (int i = 0; i < 4; i++)
#pragma unroll
        for (int j = 0; j < 4; j++)
#pragma unroll
            for (int r = 0; r < 4; r++) acc[i][j][r] = 0.f;

    int kIters = K / KC;

#pragma unroll
    for (int s = 0; s < 3; s++) {
        __half* stg = smh + s * STAGE_H;
        cp16(stg + sA,     Ag + (size_t)s * KC);
        cp16(stg + sA + 8, Ag + (size_t)s * KC + 8);
        cp16(stg + sB,     Bg + (size_t)s * KC);
        cp16(stg + sB + 8, Bg + (size_t)s * KC + 8);
        cp_commit();
    }

    for (int it = 0; it < kIters; it++) {
        asm volatile("cp.async.wait_group 2;");
        __syncthreads();

        if (it + 3 < kIters) {
            __half* stg = smh + ((it + 3) & 3) * STAGE_H;
            cp16(stg + sA,     Ag + (size_t)(it + 3) * KC);
            cp16(stg + sA + 8, Ag + (size_t)(it + 3) * KC + 8);
            cp16(stg + sB,     Bg + (size_t)(it + 3) * KC);
            cp16(stg + sB + 8, Bg + (size_t)(it + 3) * KC + 8);
        }
        cp_commit();

        uint32_t stg = sbase + ((it & 3) * STAGE_H) * 2;

#pragma unroll
        for (int sub = 0; sub < 2; sub++) {
            int cb = sub * 16;
            uint32_t aaddr = stg + (uint32_t)(arow * PADH + cb + akh) * 2;
            uint32_t baddr = stg + (uint32_t)(GBM * PADH + brow * PADH + cb + bkh) * 2;

            uint32_t af[4][4], bfr[2][4];
#pragma unroll
            for (int mt = 0; mt < 4; mt++) ldsm4(af[mt], aaddr + mt * 16 * PADH * 2);
#pragma unroll
            for (int pt = 0; pt < 2; pt++) ldsm4(bfr[pt], baddr + pt * 16 * PADH * 2);

#pragma unroll
            for (int mt = 0; mt < 4; mt++)
#pragma unroll
                for (int nt = 0; nt < 4; nt++)
                    mma_f16(acc[mt][nt], af[mt], &bfr[nt >> 1][(nt & 1) * 2]);
        }
    }

#pragma unroll
    for (int mt = 0; mt < 4; mt++) {
#pragma unroll
        for (int nt = 0; nt < 4; nt++) {
            int m = m0 + wm + mt * 16 + gid;
            int n = n0 + wn + nt * 8 + tig * 2;
            *(float2*)&C[(size_t)m * ldc + n] = make_float2(acc[mt][nt][0], acc[mt][nt][1]);
            *(float2*)&C[(size_t)(m + 8) * ldc + n] = make_float2(acc[mt][nt][2], acc[mt][nt][3]);
        }
    }
}

// merged x-projection: blockIdx.x 0..7 Wq, 8..15 Wk, 16..31 Wv, 32..47 Wg
__global__ __launch_bounds__(256, 2) void gemm_x4(
    const __half* __restrict__ x,
    const __half* __restrict__ Wq, const __half* __restrict__ Wk,
    const __half* __restrict__ Wv, const __half* __restrict__ Wg,
    float* __restrict__ qpre, float* __restrict__ kpre,
    float* __restrict__ vpre, float* __restrict__ gate)
{
    int bx = blockIdx.x;
    const __half* B; float* C; int n0; int ldc;
    if (bx < 8)       { B = Wq; C = qpre; n0 = bx * 128;        ldc = KEY_DIM; }
    else if (bx < 16) { B = Wk; C = kpre; n0 = (bx - 8) * 128;  ldc = KEY_DIM; }
    else if (bx < 32) { B = Wv; C = vpre; n0 = (bx - 16) * 128; ldc = VAL_DIM; }
    else              { B = Wg; C = gate; n0 = (bx - 32) * 128; ldc = VAL_DIM; }
    gemm_core(x, B, C, n0, ldc, HID);
}

__global__ __launch_bounds__(256, 2) void gemm_h(
    const __half* __restrict__ A, const __half* __restrict__ B,
    float* __restrict__ C, int N, int K)
{
    gemm_core(A, B, C, blockIdx.x * GBN, N, K);
}

// ---------------- fused a/b projection + decay/beta -----------------------
__global__ __launch_bounds__(128) void gemv_ab(
    const float* __restrict__ x, const float* __restrict__ Wa,
    const float* __restrict__ Wb, const float* __restrict__ A_log,
    const float* __restrict__ dt_bias, float2* __restrict__ db)
{
    __shared__ float xs[8][260];
    __shared__ float was[16][260];
    __shared__ float wbs[16][260];

    int tid = threadIdx.x;
    int row = tid >> 4, n = tid & 15;
    int r0 = blockIdx.x * 8;

    float acc_a = 0.f, acc_b = 0.f;
    for (int kc = 0; kc < HID; kc += 256) {
        __syncthreads();
        int lr = tid >> 4, lo = (tid & 15) * 16;
#pragma unroll
        for (int j = 0; j < 16; j += 4)
            *(float4*)&xs[lr][lo + j] = *(const float4*)&x[(size_t)(r0 + lr) * HID + kc + lo + j];
        int wr = tid >> 3, wo = (tid & 7) * 32;
#pragma unroll
        for (int j = 0; j < 32; j += 4) {
            *(float4*)&was[wr][wo + j] = *(const float4*)&Wa[(size_t)wr * HID + kc + wo + j];
            *(float4*)&wbs[wr][wo + j] = *(const float4*)&Wb[(size_t)wr * HID + kc + wo + j];
        }
        __syncthreads();
#pragma unroll 8
        for (int j = 0; j < 256; j += 4) {
            float4 xv = *(float4*)&xs[row][j];
            float4 wa = *(float4*)&was[n][j];
            float4 wb = *(float4*)&wbs[n][j];
            acc_a += xv.x*wa.x + xv.y*wa.y + xv.z*wa.z + xv.w*wa.w;
            acc_b += xv.x*wb.x + xv.y*wb.y + xv.z*wb.z + xv.w*wb.w;
        }
    }
    float a = acc_a + dt_bias[n];
    float sp = (a > 20.f) ? a : log1pf(expf(a));
    float decay = expf(-expf(A_log[n]) * sp);
    float beta = 1.f / (1.f + expf(-acc_b));
    db[(size_t)(r0 + row) * NVH + n] = make_float2(decay, beta);
}

// ---------------- merged conv + silu + l2norm for q AND k ------------------
// grid: [0, S_LEN*NH) -> q ; [S_LEN*NH, 2*S_LEN*NH) -> k
__global__ __launch_bounds__(128) void convqk2_kernel(
    const float* __restrict__ qpre, const float* __restrict__ kpre,
    const float* __restrict__ cwq, const float* __restrict__ cwk,
    float* __restrict__ qout, float* __restrict__ kout)
{
    int bid = blockIdx.x;
    int sel = bid >> 15;                 // S_LEN*NH = 32768
    int idx = bid & 32767;
    const float* pre = sel ? kpre : qpre;
    const float* cw  = sel ? cwk  : cwq;
    float* out       = sel ? kout : qout;
    float scale      = sel ? 1.f  : SCALE_;

    int t = idx >> 3;
    int h = idx & 7;
    int c = threadIdx.x;
    int ch = h * DK + c;
    float y = 0.f;
#pragma unroll
    for (int j = 0; j < CONV; j++) {
        int tt = t - (CONV-1) + j;
        float xv = (tt >= 0) ? pre[(size_t)tt * KEY_DIM + ch] : 0.f;
        y = fmaf(xv, cw[ch*CONV + j], y);
    }
    y = y / (1.f + expf(-y));
    float ss = y * y;
#pragma unroll
    for (int off = 16; off; off >>= 1) ss += __shfl_xor_sync(0xffffffffu, ss, off);
    __shared__ float wss[4];
    if ((threadIdx.x & 31) == 0) wss[threadIdx.x >> 5] = ss;
    __syncthreads();
    float tot = wss[0] + wss[1] + wss[2] + wss[3];
    out[(size_t)t * KEY_DIM + ch] = y * rsqrtf(tot + EPS_) * scale;
}

// ---------------- conv + silu for v ---------------------------------------
__global__ __launch_bounds__(256) void convv_kernel(
    const float* __restrict__ pre, const float* __restrict__ cw,
    float* __restrict__ out)
{
    int idx = blockIdx.x * blockDim.x + threadIdx.x;
    int t = idx >> 11;
    int ch = idx & 2047;
    float y = 0.f;
#pragma unroll
    for (int j = 0; j < CONV; j++) {
        int tt = t - (CONV-1) + j;
        float xv = (tt >= 0) ? pre[(size_t)tt * VAL_DIM + ch] : 0.f;
        y = fmaf(xv, cw[ch*CONV + j], y);
    }
    out[idx] = y / (1.f + expf(-y));
}

// ---------------- C[t][hk] = k_{t+1} . k_t per key head --------------------
__global__ __launch_bounds__(256) void dotck_kernel(
    const float* __restrict__ k, float* __restrict__ Cq)
{
    int warp = threadIdx.x >> 5;
    int lane = threadIdx.x & 31;
    int idx = blockIdx.x * 8 + warp;       // t*NH + hk
    int t = idx >> 3, hk = idx & 7;
    float cv = 0.f;
    if (t + 1 < S_LEN) {
        const float* k0 = k + (size_t)t * KEY_DIM + hk * DK + lane * 4;
        const float* k1 = k0 + KEY_DIM;
        float4 a = *(const float4*)k0;
        float4 b = *(const float4*)k1;
        cv = a.x*b.x + a.y*b.y + a.z*b.z + a.w*b.w;
#pragma unroll
        for (int off = 16; off; off >>= 1) cv += __shfl_xor_sync(0xffffffffu, cv, off);
    }
    if (lane == 0) Cq[(size_t)t * NH + hk] = cv;
}

// ---------------- delta-rule scan v5 (best known): group-major k/q ---------
#define CH 16
#define KSTR 276   // 17 rows * 16 + 4 ; 276 % 8 == 4 (conflict-free)
#define QSTR 260   // 16 rows * 16 + 4

__global__ __launch_bounds__(128) void scan_kernel(
    const float* __restrict__ k, const float* __restrict__ q,
    const float* __restrict__ v, const float2* __restrict__ db,
    const float* __restrict__ Cq, float* __restrict__ o)
{
    __shared__ float ksw[2][8 * KSTR];
    __shared__ float qsw[2][8 * QSTR];
    __shared__ float vs[2][CH][16];
    __shared__ float2 dbs[2][CH];
    __shared__ float cs[2][CH];

    int h = blockIdx.x >> 3;
    int hk = h >> 1;
    int colbase = (blockIdx.x & 7) * 16;
    int tid = threadIdx.x;
    int w = tid >> 5, lane = tid & 31;
    int g = lane >> 3, s = lane & 7;
    int col = colbase + w * 4 + g;

    int plr = tid >> 3;
    int pgp = tid & 7;
    int vr = tid >> 2;

    const float* kbase = k + hk * DK;
    const float* qbase = q + hk * DK;
    const float* vbase = v + h * DV + colbase + (tid & 3) * 4;
    const float2* dbase = db + h;
    const float* cbase = Cq + hk;
    float* obase = o + h * DV + col;

    {
        const float* krow = kbase + (size_t)plr * KEY_DIM + pgp * 16;
        const float* qrow = qbase + (size_t)plr * KEY_DIM + pgp * 16;
#pragma unroll
        for (int j = 0; j < 4; j++) {
            cp16(&ksw[0][pgp * KSTR + plr * 16 + j * 4], krow + j * 4);
            cp16(&qsw[0][pgp * QSTR + plr * 16 + j * 4], qrow + j * 4);
        }
        if (tid < 8) {
            const float* kov = kbase + (size_t)CH * KEY_DIM + tid * 16;
#pragma unroll
            for (int j = 0; j < 4; j++)
                cp16(&ksw[0][tid * KSTR + CH * 16 + j * 4], kov + j * 4);
        }
        if (tid < 64) cp16(&vs[0][vr][(tid & 3) * 4], vbase + (size_t)vr * VAL_DIM);
        if (tid < CH) cp8(&dbs[0][tid], dbase + (size_t)tid * NVH);
        if (tid < CH) cp4(&cs[0][tid], cbase + (size_t)tid * NH);
        cp_commit();
    }

    float S[16];
#pragma unroll
    for (int i = 0; i < 16; i++) S[i] = 0.f;
    float P1 = 0.f;
    float kc[16];
    bool kc_init = false;

    int buf = 0;
    const int NCH = S_LEN / CH;
    for (int c = 0; c < NCH; c++) {
        if (c + 1 < NCH) {
            int t0 = (c + 1) * CH;
            int p = buf ^ 1;
            const float* krow = kbase + (size_t)(t0 + plr) * KEY_DIM + pgp * 16;
            const float* qrow = qbase + (size_t)(t0 + plr) * KEY_DIM + pgp * 16;
#pragma unroll
            for (int j = 0; j < 4; j++) {
                cp16(&ksw[p][pgp * KSTR + plr * 16 + j * 4], krow + j * 4);
                cp16(&qsw[p][pgp * QSTR + plr * 16 + j * 4], qrow + j * 4);
            }
            if (tid < 8) {
                int ovr = t0 + CH; if (ovr > S_LEN - 1) ovr = S_LEN - 1;
                const float* kov = kbase + (size_t)ovr * KEY_DIM + tid * 16;
#pragma unroll
                for (int j = 0; j < 4; j++)
                    cp16(&ksw[p][tid * KSTR + CH * 16 + j * 4], kov + j * 4);
            }
            if (tid < 64) cp16(&vs[p][vr][(tid & 3) * 4], vbase + (size_t)(t0 + vr) * VAL_DIM);
            if (tid < CH) cp8(&dbs[p][tid], dbase + (size_t)(t0 + tid) * NVH);
            if (tid < CH) cp4(&cs[p][tid], cbase + (size_t)(t0 + tid) * NH);
            cp_commit();
            asm volatile("cp.async.wait_group 1;");
        } else {
            asm volatile("cp.async.wait_group 0;");
        }
        __syncthreads();

        if (!kc_init) {
#pragma unroll
            for (int i = 0; i < 16; i += 4)
                *(float4*)&kc[i] = *(const float4*)&ksw[0][s * KSTR + i];
            kc_init = true;
        }

        int t0 = c * CH;
        float* ob = obase + (size_t)t0 * VAL_DIM;
#pragma unroll
        for (int tt = 0; tt < CH; tt++) {
            float kn[16], qc[16];
#pragma unroll
            for (int i = 0; i < 16; i += 4) {
                *(float4*)&kn[i] = *(const float4*)&ksw[buf][s * KSTR + (tt + 1) * 16 + i];
                *(float4*)&qc[i] = *(const float4*)&qsw[buf][s * QSTR + tt * 16 + i];
            }
            float vc = vs[buf][tt][w * 4 + g];
            float2 dc = dbs[buf][tt];
            float Ct = cs[buf][tt];

            float a0 = 0.f, a1 = 0.f, a2 = 0.f, a3 = 0.f;
#pragma unroll
            for (int i = 0; i < 16; i += 4) {
                a0 = fmaf(kn[i],   S[i],   a0);
                a1 = fmaf(kn[i+1], S[i+1], a1);
                a2 = fmaf(kn[i+2], S[i+2], a2);
                a3 = fmaf(kn[i+3], S[i+3], a3);
            }
            float A = (a0 + a1) + (a2 + a3);

            float delta = (vc - dc.x * P1) * dc.y;

            float b0 = 0.f, b1 = 0.f, b2 = 0.f, b3 = 0.f;
#pragma unroll
            for (int i = 0; i < 16; i += 4) {
                S[i]   = fmaf(S[i],   dc.x, kc[i]   * delta);
                S[i+1] = fmaf(S[i+1], dc.x, kc[i+1] * delta);
                S[i+2] = fmaf(S[i+2], dc.x, kc[i+2] * delta);
                S[i+3] = fmaf(S[i+3], dc.x, kc[i+3] * delta);
                b0 = fmaf(qc[i],   S[i],   b0);
                b1 = fmaf(qc[i+1], S[i+1], b1);
                b2 = fmaf(qc[i+2], S[i+2], b2);
                b3 = fmaf(qc[i+3], S[i+3], b3);
            }
            float ov = (b0 + b1) + (b2 + b3);

            A  += __shfl_xor_sync(0xffffffffu, A, 1);
            A  += __shfl_xor_sync(0xffffffffu, A, 2);
            A  += __shfl_xor_sync(0xffffffffu, A, 4);
            ov += __shfl_xor_sync(0xffffffffu, ov, 1);
            ov += __shfl_xor_sync(0xffffffffu, ov, 2);
            ov += __shfl_xor_sync(0xffffffffu, ov, 4);
            if (s == 0) ob[(size_t)tt * VAL_DIM] = ov;

            P1 = fmaf(dc.x, A, Ct * delta);
#pragma unroll
            for (int i = 0; i < 16; i++) kc[i] = kn[i];
        }
        __syncthreads();
        buf ^= 1;
    }
}

// ---------------- gated RMS norm (emits fp16 og) ---------------------------
__global__ __launch_bounds__(128) void gnorm_kernel(
    const float* __restrict__ o, const float* __restrict__ gate,
    const float* __restrict__ w_norm, __half* __restrict__ og)
{
    int t = blockIdx.x >> 4;
    int h = blockIdx.x & 15;
    int c = threadIdx.x;
    size_t idx = (size_t)t * VAL_DIM + h * DV + c;
    float gt = gate[idx];
    float y = o[idx] * (gt / (1.f + expf(-gt)));
    float ss = y * y;
#pragma unroll
    for (int off = 16; off; off >>= 1) ss += __shfl_xor_sync(0xffffffffu, ss, off);
    __shared__ float wss[4];
    if ((threadIdx.x & 31) == 0) wss[threadIdx.x >> 5] = ss;
    __syncthreads();
    float mean = (wss[0] + wss[1] + wss[2] + wss[3]) * (1.f / DV);
    og[idx] = __float2half_rn(y * rsqrtf(mean + EPS_) * w_norm[c]);
}

// ---------------- launch ---------------------------------------------------
extern "C" void kernel_launch(void* const* d_in, const int* in_sizes, int n_in,
                              void* d_out, int out_size)
{
    const float* x      = (const float*)d_in[0];
    const float* Wq     = (const float*)d_in[1];
    const float* Wk     = (const float*)d_in[2];
    const float* Wv     = (const float*)d_in[3];
    const float* Wa     = (const float*)d_in[4];
    const float* Wb     = (const float*)d_in[5];
    const float* Wg     = (const float*)d_in[6];
    const float* Wo     = (const float*)d_in[7];
    const float* conv_q = (const float*)d_in[8];
    const float* conv_k = (const float*)d_in[9];
    const float* conv_v = (const float*)d_in[10];
    const float* A_log  = (const float*)d_in[11];
    const float* dt_b   = (const float*)d_in[12];
    const float* w_norm = (const float*)d_in[13];

    void* wsp = nullptr;
    cudaGetSymbolAddress(&wsp, g_ws_gdn);
    float* ws = (float*)wsp;
    float* qpre = ws + OF_QPRE;
    float* kpre = ws + OF_KPRE;
    float* vpre = ws + OF_VPRE;
    float* gate = ws + OF_GATE;
    float* qn   = ws + OF_QN;
    float* kn   = ws + OF_KN;
    float* vn   = ws + OF_VN;
    float2* db  = (float2*)(ws + OF_DB);
    float* Cq   = ws + OF_CQ;
    float* o    = ws + OF_O;
    __half* xh  = (__half*)(ws + OF_XH);
    __half* wqh = (__half*)(ws + OF_WQH);
    __half* wkh = (__half*)(ws + OF_WKH);
    __half* wvh = (__half*)(ws + OF_WVH);
    __half* wgh = (__half*)(ws + OF_WGH);
    __half* woh = (__half*)(ws + OF_WOH);
    __half* ogh = (__half*)(ws + OF_OGH);
    float* out  = (float*)d_out;

    cudaFuncSetAttribute(gemm_x4, cudaFuncAttributeMaxDynamicSharedMemorySize, GDYN_SMEM);
    cudaFuncSetAttribute(gemm_h,  cudaFuncAttributeMaxDynamicSharedMemorySize, GDYN_SMEM);

    // fused fp32->fp16 conversion: 24M elements, 8 per thread
    const size_t total_cvt = SZ_X + 2 * SZ_WQK + 3 * SZ_WV;   // 25165824
    cvt_all_kernel<<<(int)(total_cvt / 2048), 256>>>(x, Wq, Wk, Wv, Wg, Wo, xh);

    dim3 blk(256);
    dim3 g_x4(48, S_LEN / GBM);
    dim3 g_o (VAL_DIM / GBN, S_LEN / GBM);

    gemm_x4<<<g_x4, blk, GDYN_SMEM>>>(xh, wqh, wkh, wvh, wgh, qpre, kpre, vpre, gate);
    gemv_ab<<<S_LEN / 8, 128>>>(x, Wa, Wb, A_log, dt_b, db);

    convqk2_kernel<<<2 * S_LEN * NH, 128>>>(qpre, kpre, conv_q, conv_k, qn, kn);
    convv_kernel<<<(S_LEN * VAL_DIM) / 256, 256>>>(vpre, conv_v, vn);
    dotck_kernel<<<S_LEN * NH / 8, 256>>>(kn, Cq);

    scan_kernel<<<128, 128>>>(kn, qn, vn, db, Cq, o);

    gnorm_kernel<<<S_LEN * NVH, 128>>>(o, gate, w_norm, ogh);

    gemm_h<<<g_o, blk, GDYN_SMEM>>>(ogh, woh, out, HID, VAL_DIM);
}

// round 16
// speedup vs baseline: 1.1669x; 1.0642x over previous
#include <cuda_runtime.h>
#include <cuda_fp16.h>
#include <math.h>
#include <stdint.h>

// ---------------- problem constants ----------------
#define S_LEN 4096
#define HID   2048
#define NH    8
#define NVH   16
#define DK    128
#define DV    128
#define KEY_DIM  (NH*DK)    // 1024
#define VAL_DIM  (NVH*DV)   // 2048
#define CONV  4
#define EPS_  1e-6f
#define SCALE_ 0.08838834764831845f   // 128^-0.5

// ---------------- workspace -------------------------------------------------
static constexpr size_t SZ_QPRE = (size_t)S_LEN * KEY_DIM;
static constexpr size_t SZ_VPRE = (size_t)S_LEN * VAL_DIM;
static constexpr size_t SZ_AB   = (size_t)S_LEN * NVH;
static constexpr size_t SZ_C    = (size_t)S_LEN * NH;
static constexpr size_t SZ_X    = (size_t)S_LEN * HID;
static constexpr size_t SZ_WQK  = (size_t)KEY_DIM * HID;
static constexpr size_t SZ_WV   = (size_t)VAL_DIM * HID;

static constexpr size_t OF_QPRE = 0;
static constexpr size_t OF_KPRE = OF_QPRE + SZ_QPRE;
static constexpr size_t OF_VPRE = OF_KPRE + SZ_QPRE;
static constexpr size_t OF_GATE = OF_VPRE + SZ_VPRE;
static constexpr size_t OF_QN   = OF_GATE + SZ_VPRE;
static constexpr size_t OF_KN   = OF_QN + SZ_QPRE;
static constexpr size_t OF_VN   = OF_KN + SZ_QPRE;
static constexpr size_t OF_DB   = OF_VN + SZ_VPRE;   // float2 per (t,h)
static constexpr size_t OF_CQ   = OF_DB + 2*SZ_AB;   // C1 per (t,hk)
static constexpr size_t OF_O    = OF_CQ + SZ_C;
// fp16 buffers (element counts halved into float units) -- CONTIGUOUS
static constexpr size_t OF_XH   = OF_O + SZ_VPRE;
static constexpr size_t OF_WQH  = OF_XH + SZ_X/2;
static constexpr size_t OF_WKH  = OF_WQH + SZ_WQK/2;
static constexpr size_t OF_WVH  = OF_WKH + SZ_WQK/2;
static constexpr size_t OF_WGH  = OF_WVH + SZ_WV/2;
static constexpr size_t OF_WOH  = OF_WGH + SZ_WV/2;
static constexpr size_t OF_OGH  = OF_WOH + SZ_WV/2;
static constexpr size_t WS_TOTAL = OF_OGH + SZ_VPRE/2;

__device__ float g_ws_gdn[WS_TOTAL];

// ---------------- cp.async helpers -----------------------------------------
__device__ __forceinline__ void cp16(void* s, const void* g) {
    asm volatile("cp.async.ca.shared.global [%0], [%1], 16;"
                 :: "r"((uint32_t)__cvta_generic_to_shared(s)), "l"(g));
}
__device__ __forceinline__ void cp8(void* s, const void* g) {
    asm volatile("cp.async.ca.shared.global [%0], [%1], 8;"
                 :: "r"((uint32_t)__cvta_generic_to_shared(s)), "l"(g));
}
__device__ __forceinline__ void cp4(void* s, const void* g) {
    asm volatile("cp.async.ca.shared.global [%0], [%1], 4;"
                 :: "r"((uint32_t)__cvta_generic_to_shared(s)), "l"(g));
}
__device__ __forceinline__ void cp_commit() {
    asm volatile("cp.async.commit_group;");
}

// ---------------- fused fp32 -> fp16 conversion (16 elems/thread) ----------
__global__ __launch_bounds__(256) void cvt_all_kernel(
    const float* __restrict__ x,
    const float* __restrict__ Wq, const float* __restrict__ Wk,
    const float* __restrict__ Wv, const float* __restrict__ Wg,
    const float* __restrict__ Wo, __half* __restrict__ out)
{
    const size_t B0 = SZ_X;
    const size_t B1 = B0 + SZ_WQK;
    const size_t B2 = B1 + SZ_WQK;
    const size_t B3 = B2 + SZ_WV;
    const size_t B4 = B3 + SZ_WV;
    const size_t B5 = B4 + SZ_WV;
    size_t i = ((size_t)blockIdx.x * 256 + threadIdx.x) * 16;
    if (i >= B5) return;
    const float* src; size_t off;
    if (i < B0)      { src = x;  off = i; }
    else if (i < B1) { src = Wq; off = i - B0; }
    else if (i < B2) { src = Wk; off = i - B1; }
    else if (i < B3) { src = Wv; off = i - B2; }
    else if (i < B4) { src = Wg; off = i - B3; }
    else             { src = Wo; off = i - B4; }
    float4 v0 = *(const float4*)(src + off);
    float4 v1 = *(const float4*)(src + off + 4);
    float4 v2 = *(const float4*)(src + off + 8);
    float4 v3 = *(const float4*)(src + off + 12);
    __half2 h[8];
    h[0] = __floats2half2_rn(v0.x, v0.y);
    h[1] = __floats2half2_rn(v0.z, v0.w);
    h[2] = __floats2half2_rn(v1.x, v1.y);
    h[3] = __floats2half2_rn(v1.z, v1.w);
    h[4] = __floats2half2_rn(v2.x, v2.y);
    h[5] = __floats2half2_rn(v2.z, v2.w);
    h[6] = __floats2half2_rn(v3.x, v3.y);
    h[7] = __floats2half2_rn(v3.z, v3.w);
    *(uint4*)(out + i)     = *(uint4*)&h[0];
    *(uint4*)(out + i + 8) = *(uint4*)&h[4];
}

// ================= fp16 tensor-core GEMM (k32 stages, 4-deep ring) =========
#define GBM 128
#define GBN 128
#define KC  32
#define PADH 40
#define STAGE_H (2 * GBM * PADH)
#define GDYN_SMEM (4 * STAGE_H * 2)    // 81920 bytes

__device__ __forceinline__ void mma_f16(float* c, const uint32_t* a, const uint32_t* b) {
    asm volatile(
        "mma.sync.aligned.m16n8k16.row.col.f32.f16.f16.f32 "
        "{%0,%1,%2,%3}, {%4,%5,%6,%7}, {%8,%9}, {%0,%1,%2,%3};"
        : "+f"(c[0]), "+f"(c[1]), "+f"(c[2]), "+f"(c[3])
        : "r"(a[0]), "r"(a[1]), "r"(a[2]), "r"(a[3]), "r"(b[0]), "r"(b[1]));
}

__device__ __forceinline__ void ldsm4(uint32_t* r, uint32_t addr) {
    asm volatile("ldmatrix.sync.aligned.m8n8.x4.shared.b16 {%0,%1,%2,%3}, [%4];"
                 : "=r"(r[0]), "=r"(r[1]), "=r"(r[2]), "=r"(r[3]) : "r"(addr));
}

__device__ __forceinline__ void gemm_core(
    const __half* __restrict__ A, const __half* __restrict__ B,
    float* __restrict__ C, int n0, int ldc, int K)
{
    extern __shared__ __half smh[];
    uint32_t sbase = (uint32_t)__cvta_generic_to_shared(smh);

    int tid = threadIdx.x;
    int warp = tid >> 5;
    int lane = tid & 31;
    int gid = lane >> 2;
    int tig = lane & 3;

    int m0 = blockIdx.y * GBM;
    int wm = (warp >> 2) * 64;
    int wn = (warp & 3) * 32;

    int lrow = tid >> 1;
    int lk   = (tid & 1) * 16;
    const __half* Ag = A + (size_t)(m0 + lrow) * K + lk;
    const __half* Bg = B + (size_t)(n0 + lrow) * K + lk;
    int sA = lrow * PADH + lk;
    int sB = GBM * PADH + lrow * PADH + lk;

    int arow = wm + (lane & 15);
    int akh  = (lane >> 4) * 8;
    int brow = wn + (lane & 7) + ((lane >> 4) << 3);
    int bkh  = ((lane >> 3) & 1) * 8;

    float acc[4][4][4];
#pragma unroll
    for (int i = 0; i < 4; i++)
#pragma unroll
        for (int j = 0; j < 4; j++)
#pragma unroll
            for (int r = 0; r < 4; r++) acc[i][j][r] = 0.f;

    int kIters = K / KC;

#pragma unroll
    for (int s = 0; s < 3; s++) {
        __half* stg = smh + s * STAGE_H;
        cp16(stg + sA,     Ag + (size_t)s * KC);
        cp16(stg + sA + 8, Ag + (size_t)s * KC + 8);
        cp16(stg + sB,     Bg + (size_t)s * KC);
        cp16(stg + sB + 8, Bg + (size_t)s * KC + 8);
        cp_commit();
    }

    for (int it = 0; it < kIters; it++) {
        asm volatile("cp.async.wait_group 2;");
        __syncthreads();

        if (it + 3 < kIters) {
            __half* stg = smh + ((it + 3) & 3) * STAGE_H;
            cp16(stg + sA,     Ag + (size_t)(it + 3) * KC);
            cp16(stg + sA + 8, Ag + (size_t)(it + 3) * KC + 8);
            cp16(stg + sB,     Bg + (size_t)(it + 3) * KC);
            cp16(stg + sB + 8, Bg + (size_t)(it + 3) * KC + 8);
        }
        cp_commit();

        uint32_t stg = sbase + ((it & 3) * STAGE_H) * 2;

#pragma unroll
        for (int sub = 0; sub < 2; sub++) {
            int cb = sub * 16;
            uint32_t aaddr = stg + (uint32_t)(arow * PADH + cb + akh) * 2;
            uint32_t baddr = stg + (uint32_t)(GBM * PADH + brow * PADH + cb + bkh) * 2;

            uint32_t af[4][4], bfr[2][4];
#pragma unroll
            for (int mt = 0; mt < 4; mt++) ldsm4(af[mt], aaddr + mt * 16 * PADH * 2);
#pragma unroll
            for (int pt = 0; pt < 2; pt++) ldsm4(bfr[pt], baddr + pt * 16 * PADH * 2);

#pragma unroll
            for (int mt = 0; mt < 4; mt++)
#pragma unroll
                for (int nt = 0; nt < 4; nt++)
                    mma_f16(acc[mt][nt], af[mt], &bfr[nt >> 1][(nt & 1) * 2]);
        }
    }

#pragma unroll
    for (int mt = 0; mt < 4; mt++) {
#pragma unroll
        for (int nt = 0; nt < 4; nt++) {
            int m = m0 + wm + mt * 16 + gid;
            int n = n0 + wn + nt * 8 + tig * 2;
            *(float2*)&C[(size_t)m * ldc + n] = make_float2(acc[mt][nt][0], acc[mt][nt][1]);
            *(float2*)&C[(size_t)(m + 8) * ldc + n] = make_float2(acc[mt][nt][2], acc[mt][nt][3]);
        }
    }
}

// merged x-projection: blockIdx.x 0..7 Wq, 8..15 Wk, 16..31 Wv, 32..47 Wg
__global__ __launch_bounds__(256, 2) void gemm_x4(
    const __half* __restrict__ x,
    const __half* __restrict__ Wq, const __half* __restrict__ Wk,
    const __half* __restrict__ Wv, const __half* __restrict__ Wg,
    float* __restrict__ qpre, float* __restrict__ kpre,
    float* __restrict__ vpre, float* __restrict__ gate)
{
    int bx = blockIdx.x;
    const __half* B; float* C; int n0; int ldc;
    if (bx < 8)       { B = Wq; C = qpre; n0 = bx * 128;        ldc = KEY_DIM; }
    else if (bx < 16) { B = Wk; C = kpre; n0 = (bx - 8) * 128;  ldc = KEY_DIM; }
    else if (bx < 32) { B = Wv; C = vpre; n0 = (bx - 16) * 128; ldc = VAL_DIM; }
    else              { B = Wg; C = gate; n0 = (bx - 32) * 128; ldc = VAL_DIM; }
    gemm_core(x, B, C, n0, ldc, HID);
}

__global__ __launch_bounds__(256, 2) void gemm_h(
    const __half* __restrict__ A, const __half* __restrict__ B,
    float* __restrict__ C, int N, int K)
{
    gemm_core(A, B, C, blockIdx.x * GBN, N, K);
}

// ---------------- fused a/b projection + decay/beta -----------------------
__global__ __launch_bounds__(128) void gemv_ab(
    const float* __restrict__ x, const float* __restrict__ Wa,
    const float* __restrict__ Wb, const float* __restrict__ A_log,
    const float* __restrict__ dt_bias, float2* __restrict__ db)
{
    __shared__ float xs[8][260];
    __shared__ float was[16][260];
    __shared__ float wbs[16][260];

    int tid = threadIdx.x;
    int row = tid >> 4, n = tid & 15;
    int r0 = blockIdx.x * 8;

    float acc_a = 0.f, acc_b = 0.f;
    for (int kc = 0; kc < HID; kc += 256) {
        __syncthreads();
        int lr = tid >> 4, lo = (tid & 15) * 16;
#pragma unroll
        for (int j = 0; j < 16; j += 4)
            *(float4*)&xs[lr][lo + j] = *(const float4*)&x[(size_t)(r0 + lr) * HID + kc + lo + j];
        int wr = tid >> 3, wo = (tid & 7) * 32;
#pragma unroll
        for (int j = 0; j < 32; j += 4) {
            *(float4*)&was[wr][wo + j] = *(const float4*)&Wa[(size_t)wr * HID + kc + wo + j];
            *(float4*)&wbs[wr][wo + j] = *(const float4*)&Wb[(size_t)wr * HID + kc + wo + j];
        }
        __syncthreads();
#pragma unroll 8
        for (int j = 0; j < 256; j += 4) {
            float4 xv = *(float4*)&xs[row][j];
            float4 wa = *(float4*)&was[n][j];
            float4 wb = *(float4*)&wbs[n][j];
            acc_a += xv.x*wa.x + xv.y*wa.y + xv.z*wa.z + xv.w*wa.w;
            acc_b += xv.x*wb.x + xv.y*wb.y + xv.z*wb.z + xv.w*wb.w;
        }
    }
    float a = acc_a + dt_bias[n];
    float sp = (a > 20.f) ? a : log1pf(expf(a));
    float decay = expf(-expf(A_log[n]) * sp);
    float beta = 1.f / (1.f + expf(-acc_b));
    db[(size_t)(r0 + row) * NVH + n] = make_float2(decay, beta);
}

// ---------------- merged conv+silu+l2norm for q AND k, 2 timesteps/block ---
// grid: [0, S_LEN*NH/2) -> q ; [S_LEN*NH/2, S_LEN*NH) -> k
__global__ __launch_bounds__(128) void convqk2_kernel(
    const float* __restrict__ qpre, const float* __restrict__ kpre,
    const float* __restrict__ cwq, const float* __restrict__ cwk,
    float* __restrict__ qout, float* __restrict__ kout)
{
    int bid = blockIdx.x;
    int sel = bid >> 14;                 // S_LEN*NH/2 = 16384 per tensor
    int idx = bid & 16383;
    const float* pre = sel ? kpre : qpre;
    const float* cw  = sel ? cwk  : cwq;
    float* out       = sel ? kout : qout;
    float scale      = sel ? 1.f  : SCALE_;

    int t0 = (idx >> 3) * 2;
    int h = idx & 7;
    int c = threadIdx.x;
    int ch = h * DK + c;

    float w0 = cw[ch*CONV + 0], w1 = cw[ch*CONV + 1];
    float w2 = cw[ch*CONV + 2], w3 = cw[ch*CONV + 3];

    float r[5];
#pragma unroll
    for (int j = 0; j < 5; j++) {
        int row = t0 - 3 + j;
        r[j] = (row >= 0) ? pre[(size_t)row * KEY_DIM + ch] : 0.f;
    }
    float y0 = r[0]*w0 + r[1]*w1 + r[2]*w2 + r[3]*w3;
    float y1 = r[1]*w0 + r[2]*w1 + r[3]*w2 + r[4]*w3;
    y0 = y0 / (1.f + expf(-y0));
    y1 = y1 / (1.f + expf(-y1));

    float s0 = y0 * y0, s1 = y1 * y1;
#pragma unroll
    for (int off = 16; off; off >>= 1) {
        s0 += __shfl_xor_sync(0xffffffffu, s0, off);
        s1 += __shfl_xor_sync(0xffffffffu, s1, off);
    }
    __shared__ float wss[2][4];
    if ((threadIdx.x & 31) == 0) {
        wss[0][threadIdx.x >> 5] = s0;
        wss[1][threadIdx.x >> 5] = s1;
    }
    __syncthreads();
    float tot0 = wss[0][0] + wss[0][1] + wss[0][2] + wss[0][3];
    float tot1 = wss[1][0] + wss[1][1] + wss[1][2] + wss[1][3];
    out[(size_t)t0 * KEY_DIM + ch]       = y0 * rsqrtf(tot0 + EPS_) * scale;
    out[(size_t)(t0 + 1) * KEY_DIM + ch] = y1 * rsqrtf(tot1 + EPS_) * scale;
}

// ---------------- conv + silu for v ---------------------------------------
__global__ __launch_bounds__(256) void convv_kernel(
    const float* __restrict__ pre, const float* __restrict__ cw,
    float* __restrict__ out)
{
    int idx = blockIdx.x * blockDim.x + threadIdx.x;
    int t = idx >> 11;
    int ch = idx & 2047;
    float y = 0.f;
#pragma unroll
    for (int j = 0; j < CONV; j++) {
        int tt = t - (CONV-1) + j;
        float xv = (tt >= 0) ? pre[(size_t)tt * VAL_DIM + ch] : 0.f;
        y = fmaf(xv, cw[ch*CONV + j], y);
    }
    out[idx] = y / (1.f + expf(-y));
}

// ---------------- C[t][hk] = k_{t+1} . k_t per key head --------------------
__global__ __launch_bounds__(256) void dotck_kernel(
    const float* __restrict__ k, float* __restrict__ Cq)
{
    int warp = threadIdx.x >> 5;
    int lane = threadIdx.x & 31;
    int idx = blockIdx.x * 8 + warp;       // t*NH + hk
    int t = idx >> 3, hk = idx & 7;
    float cv = 0.f;
    if (t + 1 < S_LEN) {
        const float* k0 = k + (size_t)t * KEY_DIM + hk * DK + lane * 4;
        const float* k1 = k0 + KEY_DIM;
        float4 a = *(const float4*)k0;
        float4 b = *(const float4*)k1;
        cv = a.x*b.x + a.y*b.y + a.z*b.z + a.w*b.w;
#pragma unroll
        for (int off = 16; off; off >>= 1) cv += __shfl_xor_sync(0xffffffffu, cv, off);
    }
    if (lane == 0) Cq[(size_t)t * NH + hk] = cv;
}

// ---------------- delta-rule scan v5b: group-major k/q, CH=32 chunks -------
#define CH 32
#define KSTR 532   // 33 rows * 16 + 4 ; 532 % 8 == 4 (conflict-free)
#define QSTR 516   // 32 rows * 16 + 4 ; 516 % 8 == 4

__global__ __launch_bounds__(128) void scan_kernel(
    const float* __restrict__ k, const float* __restrict__ q,
    const float* __restrict__ v, const float2* __restrict__ db,
    const float* __restrict__ Cq, float* __restrict__ o)
{
    __shared__ float ksw[2][8 * KSTR];
    __shared__ float qsw[2][8 * QSTR];
    __shared__ float vs[2][CH][16];
    __shared__ float2 dbs[2][CH];
    __shared__ float cs[2][CH];

    int h = blockIdx.x >> 3;
    int hk = h >> 1;
    int colbase = (blockIdx.x & 7) * 16;
    int tid = threadIdx.x;
    int w = tid >> 5, lane = tid & 31;
    int g = lane >> 3, s = lane & 7;
    int col = colbase + w * 4 + g;

    int plr = tid >> 3;        // 0..15 (handles rows plr, plr+16)
    int pgp = tid & 7;
    int vr = tid >> 2;         // 0..31 (all 128 threads)

    const float* kbase = k + hk * DK;
    const float* qbase = q + hk * DK;
    const float* vbase = v + h * DV + colbase + (tid & 3) * 4;
    const float2* dbase = db + h;
    const float* cbase = Cq + hk;
    float* obase = o + h * DV + col;

    // ---- issue chunk 0 ----
    {
#pragma unroll
        for (int r2 = 0; r2 < 2; r2++) {
            int row = plr + r2 * 16;
            const float* krow = kbase + (size_t)row * KEY_DIM + pgp * 16;
            const float* qrow = qbase + (size_t)row * KEY_DIM + pgp * 16;
#pragma unroll
            for (int j = 0; j < 4; j++) {
                cp16(&ksw[0][pgp * KSTR + row * 16 + j * 4], krow + j * 4);
                cp16(&qsw[0][pgp * QSTR + row * 16 + j * 4], qrow + j * 4);
            }
        }
        if (tid < 8) {
            const float* kov = kbase + (size_t)CH * KEY_DIM + tid * 16;
#pragma unroll
            for (int j = 0; j < 4; j++)
                cp16(&ksw[0][tid * KSTR + CH * 16 + j * 4], kov + j * 4);
        }
        cp16(&vs[0][vr][(tid & 3) * 4], vbase + (size_t)vr * VAL_DIM);
        if (tid < CH) cp8(&dbs[0][tid], dbase + (size_t)tid * NVH);
        if (tid < CH) cp4(&cs[0][tid], cbase + (size_t)tid * NH);
        cp_commit();
    }

    float S[16];
#pragma unroll
    for (int i = 0; i < 16; i++) S[i] = 0.f;
    float P1 = 0.f;
    float kc[16];
    bool kc_init = false;

    int buf = 0;
    const int NCH = S_LEN / CH;
    for (int c = 0; c < NCH; c++) {
        if (c + 1 < NCH) {
            int t0 = (c + 1) * CH;
            int p = buf ^ 1;
#pragma unroll
            for (int r2 = 0; r2 < 2; r2++) {
                int row = plr + r2 * 16;
                const float* krow = kbase + (size_t)(t0 + row) * KEY_DIM + pgp * 16;
                const float* qrow = qbase + (size_t)(t0 + row) * KEY_DIM + pgp * 16;
#pragma unroll
                for (int j = 0; j < 4; j++) {
                    cp16(&ksw[p][pgp * KSTR + row * 16 + j * 4], krow + j * 4);
                    cp16(&qsw[p][pgp * QSTR + row * 16 + j * 4], qrow + j * 4);
                }
            }
            if (tid < 8) {
                int ovr = t0 + CH; if (ovr > S_LEN - 1) ovr = S_LEN - 1;
                const float* kov = kbase + (size_t)ovr * KEY_DIM + tid * 16;
#pragma unroll
                for (int j = 0; j < 4; j++)
                    cp16(&ksw[p][tid * KSTR + CH * 16 + j * 4], kov + j * 4);
            }
            cp16(&vs[p][vr][(tid & 3) * 4], vbase + (size_t)(t0 + vr) * VAL_DIM);
            if (tid < CH) cp8(&dbs[p][tid], dbase + (size_t)(t0 + tid) * NVH);
            if (tid < CH) cp4(&cs[p][tid], cbase + (size_t)(t0 + tid) * NH);
            cp_commit();
            asm volatile("cp.async.wait_group 1;");
        } else {
            asm volatile("cp.async.wait_group 0;");
        }
        __syncthreads();

        if (!kc_init) {
#pragma unroll
            for (int i = 0; i < 16; i += 4)
                *(float4*)&kc[i] = *(const float4*)&ksw[0][s * KSTR + i];
            kc_init = true;
        }

        int t0 = c * CH;
        float* ob = obase + (size_t)t0 * VAL_DIM;
#pragma unroll 16
        for (int tt = 0; tt < CH; tt++) {
            float kn[16], qc[16];
#pragma unroll
            for (int i = 0; i < 16; i += 4) {
                *(float4*)&kn[i] = *(const float4*)&ksw[buf][s * KSTR + (tt + 1) * 16 + i];
                *(float4*)&qc[i] = *(const float4*)&qsw[buf][s * QSTR + tt * 16 + i];
            }
            float vc = vs[buf][tt][w * 4 + g];
            float2 dc = dbs[buf][tt];
            float Ct = cs[buf][tt];

            float a0 = 0.f, a1 = 0.f, a2 = 0.f, a3 = 0.f;
#pragma unroll
            for (int i = 0; i < 16; i += 4) {
                a0 = fmaf(kn[i],   S[i],   a0);
                a1 = fmaf(kn[i+1], S[i+1], a1);
                a2 = fmaf(kn[i+2], S[i+2], a2);
                a3 = fmaf(kn[i+3], S[i+3], a3);
            }
            float A = (a0 + a1) + (a2 + a3);

            float delta = (vc - dc.x * P1) * dc.y;

            float b0 = 0.f, b1 = 0.f, b2 = 0.f, b3 = 0.f;
#pragma unroll
            for (int i = 0; i < 16; i += 4) {
                S[i]   = fmaf(S[i],   dc.x, kc[i]   * delta);
                S[i+1] = fmaf(S[i+1], dc.x, kc[i+1] * delta);
                S[i+2] = fmaf(S[i+2], dc.x, kc[i+2] * delta);
                S[i+3] = fmaf(S[i+3], dc.x, kc[i+3] * delta);
                b0 = fmaf(qc[i],   S[i],   b0);
                b1 = fmaf(qc[i+1], S[i+1], b1);
                b2 = fmaf(qc[i+2], S[i+2], b2);
                b3 = fmaf(qc[i+3], S[i+3], b3);
            }
            float ov = (b0 + b1) + (b2 + b3);

            A  += __shfl_xor_sync(0xffffffffu, A, 1);
            A  += __shfl_xor_sync(0xffffffffu, A, 2);
            A  += __shfl_xor_sync(0xffffffffu, A, 4);
            ov += __shfl_xor_sync(0xffffffffu, ov, 1);
            ov += __shfl_xor_sync(0xffffffffu, ov, 2);
            ov += __shfl_xor_sync(0xffffffffu, ov, 4);
            if (s == 0) ob[(size_t)tt * VAL_DIM] = ov;

            P1 = fmaf(dc.x, A, Ct * delta);
#pragma unroll
            for (int i = 0; i < 16; i++) kc[i] = kn[i];
        }
        __syncthreads();
        buf ^= 1;
    }
}

// ---------------- gated RMS norm (emits fp16 og) ---------------------------
__global__ __launch_bounds__(128) void gnorm_kernel(
    const float* __restrict__ o, const float* __restrict__ gate,
    const float* __restrict__ w_norm, __half* __restrict__ og)
{
    int t = blockIdx.x >> 4;
    int h = blockIdx.x & 15;
    int c = threadIdx.x;
    size_t idx = (size_t)t * VAL_DIM + h * DV + c;
    float gt = gate[idx];
    float y = o[idx] * (gt / (1.f + expf(-gt)));
    float ss = y * y;
#pragma unroll
    for (int off = 16; off; off >>= 1) ss += __shfl_xor_sync(0xffffffffu, ss, off);
    __shared__ float wss[4];
    if ((threadIdx.x & 31) == 0) wss[threadIdx.x >> 5] = ss;
    __syncthreads();
    float mean = (wss[0] + wss[1] + wss[2] + wss[3]) * (1.f / DV);
    og[idx] = __float2half_rn(y * rsqrtf(mean + EPS_) * w_norm[c]);
}

// ---------------- launch ---------------------------------------------------
extern "C" void kernel_launch(void* const* d_in, const int* in_sizes, int n_in,
                              void* d_out, int out_size)
{
    const float* x      = (const float*)d_in[0];
    const float* Wq     = (const float*)d_in[1];
    const float* Wk     = (const float*)d_in[2];
    const float* Wv     = (const float*)d_in[3];
    const float* Wa     = (const float*)d_in[4];
    const float* Wb     = (const float*)d_in[5];
    const float* Wg     = (const float*)d_in[6];
    const float* Wo     = (const float*)d_in[7];
    const float* conv_q = (const float*)d_in[8];
    const float* conv_k = (const float*)d_in[9];
    const float* conv_v = (const float*)d_in[10];
    const float* A_log  = (const float*)d_in[11];
    const float* dt_b   = (const float*)d_in[12];
    const float* w_norm = (const float*)d_in[13];

    void* wsp = nullptr;
    cudaGetSymbolAddress(&wsp, g_ws_gdn);
    float* ws = (float*)wsp;
    float* qpre = ws + OF_QPRE;
    float* kpre = ws + OF_KPRE;
    float* vpre = ws + OF_VPRE;
    float* gate = ws + OF_GATE;
    float* qn   = ws + OF_QN;
    float* kn   = ws + OF_KN;
    float* vn   = ws + OF_VN;
    float2* db  = (float2*)(ws + OF_DB);
    float* Cq   = ws + OF_CQ;
    float* o    = ws + OF_O;
    __half* xh  = (__half*)(ws + OF_XH);
    __half* wqh = (__half*)(ws + OF_WQH);
    __half* wkh = (__half*)(ws + OF_WKH);
    __half* wvh = (__half*)(ws + OF_WVH);
    __half* wgh = (__half*)(ws + OF_WGH);
    __half* woh = (__half*)(ws + OF_WOH);
    __half* ogh = (__half*)(ws + OF_OGH);
    float* out  = (float*)d_out;

    cudaFuncSetAttribute(gemm_x4, cudaFuncAttributeMaxDynamicSharedMemorySize, GDYN_SMEM);
    cudaFuncSetAttribute(gemm_h,  cudaFuncAttributeMaxDynamicSharedMemorySize, GDYN_SMEM);

    // fused fp32->fp16 conversion: 16 elems/thread
    const size_t total_cvt = SZ_X + 2 * SZ_WQK + 3 * SZ_WV;   // 25165824
    cvt_all_kernel<<<(int)(total_cvt / 4096), 256>>>(x, Wq, Wk, Wv, Wg, Wo, xh);

    dim3 blk(256);
    dim3 g_x4(48, S_LEN / GBM);
    dim3 g_o (VAL_DIM / GBN, S_LEN / GBM);

    gemm_x4<<<g_x4, blk, GDYN_SMEM>>>(xh, wqh, wkh, wvh, wgh, qpre, kpre, vpre, gate);
    gemv_ab<<<S_LEN / 8, 128>>>(x, Wa, Wb, A_log, dt_b, db);

    convqk2_kernel<<<S_LEN * NH, 128>>>(qpre, kpre, conv_q, conv_k, qn, kn);
    convv_kernel<<<(S_LEN * VAL_DIM) / 256, 256>>>(vpre, conv_v, vn);
    dotck_kernel<<<S_LEN * NH / 8, 256>>>(kn, Cq);

    scan_kernel<<<128, 128>>>(kn, qn, vn, db, Cq, o);

    gnorm_kernel<<<S_LEN * NVH, 128>>>(o, gate, w_norm, ogh);

    gemm_h<<<g_o, blk, GDYN_SMEM>>>(ogh, woh, out, HID, VAL_DIM);
}